// round 3
// baseline (speedup 1.0000x reference)
#include <cuda_runtime.h>
#include <math.h>

// ---------------- Problem constants ----------------
#define BATCH   16
#define NPTS    1024
#define CIN     16
#define NODES   (BATCH * NPTS)      // 16384
#define KNN     10
#define EDGES   (NODES * KNN)       // 163840

// packed weight offsets: layer l region is (2K_l x D_l) row-major
#define WOFF0 0
#define WOFF1 4096
#define WOFF2 69632
#define WOFF3 200704
#define WTOT  233472

// ---------------- Device scratch ----------------
__device__ float g_hcat[NODES * 512];     // concat [h | agg], max width 512
__device__ float g_hbuf[NODES * 256];     // layer outputs, max width 256
__device__ float g_Ht[BATCH * 64 * NPTS]; // per-batch transposed final features
__device__ float g_wcat[WTOT];
__device__ int   g_nbr[EDGES];            // dst (global node id) per edge
__device__ int   g_indeg[NODES];
__device__ int   g_off[NODES + 1];
__device__ int   g_cur[NODES];
__device__ int   g_rsrc[EDGES];           // CSR: incoming-source node per dst slot

// ---------------- kNN: per-node 11 smallest (d2, idx), jax tie-break ----------------
__global__ void knn_kernel(const float* __restrict__ x) {
    const int b   = blockIdx.y;
    const int tid = threadIdx.x;
    const int i   = blockIdx.x * 256 + tid;
    const float* xb = x + (size_t)b * NPTS * CIN;

    __shared__ float sx[256 * 16];
    __shared__ float ssq[256];
    __shared__ float sd[11][256];
    __shared__ int   si[11][256];

    float xi[16];
    float sqi = 0.f;
#pragma unroll
    for (int c = 0; c < 16; c++) { xi[c] = xb[i * 16 + c]; sqi += xi[c] * xi[c]; }

#pragma unroll
    for (int t = 0; t < 11; t++) { sd[t][tid] = INFINITY; si[t][tid] = 0x7fffffff; }

    for (int jt = 0; jt < 4; jt++) {
        __syncthreads();
        float s = 0.f;
#pragma unroll
        for (int c = 0; c < 16; c++) {
            float v = xb[(jt * 256 + tid) * 16 + c];
            sx[tid * 16 + c] = v;
            s += v * v;
        }
        ssq[tid] = s;
        __syncthreads();

        for (int jj = 0; jj < 256; jj++) {
            float dot = 0.f;
#pragma unroll
            for (int c = 0; c < 16; c++) dot += xi[c] * sx[jj * 16 + c];
            float d2 = sqi + ssq[jj] - 2.0f * dot;
            int   j  = jt * 256 + jj;
            float wd = sd[10][tid]; int wi = si[10][tid];
            if (d2 < wd || (d2 == wd && j < wi)) {
                int t = 10;
                while (t > 0) {
                    float pd = sd[t - 1][tid]; int pi = si[t - 1][tid];
                    if (d2 < pd || (d2 == pd && j < pi)) {
                        sd[t][tid] = pd; si[t][tid] = pi; t--;
                    } else break;
                }
                sd[t][tid] = d2; si[t][tid] = j;
            }
        }
    }
    int g = b * NPTS + i;
#pragma unroll
    for (int t = 1; t <= 10; t++)
        g_nbr[g * KNN + (t - 1)] = b * NPTS + si[t][tid];
}

// ---------------- Reverse-CSR construction ----------------
__global__ void zero_indeg() {
    int idx = blockIdx.x * blockDim.x + threadIdx.x;
    if (idx < NODES) g_indeg[idx] = 0;
}
__global__ void count_deg() {
    int e = blockIdx.x * blockDim.x + threadIdx.x;
    if (e < EDGES) atomicAdd(&g_indeg[g_nbr[e]], 1);
}
__global__ void scan_kernel() {
    __shared__ int sc[1024];
    int tid = threadIdx.x;
    int base = tid * 16;
    int cnt[16]; int s = 0;
#pragma unroll
    for (int u = 0; u < 16; u++) { cnt[u] = g_indeg[base + u]; s += cnt[u]; }
    sc[tid] = s;
    __syncthreads();
    for (int off = 1; off < 1024; off <<= 1) {
        int v = (tid >= off) ? sc[tid - off] : 0;
        __syncthreads();
        sc[tid] += v;
        __syncthreads();
    }
    int run = sc[tid] - s;  // exclusive prefix
#pragma unroll
    for (int u = 0; u < 16; u++) {
        g_off[base + u] = run;
        g_cur[base + u] = run;
        run += cnt[u];
    }
    if (tid == 1023) g_off[NODES] = run;
}
__global__ void fill_rev() {
    int e = blockIdx.x * blockDim.x + threadIdx.x;
    if (e < EDGES) {
        int m = g_nbr[e];
        int p = atomicAdd(&g_cur[m], 1);
        g_rsrc[p] = e / KNN;   // global source node
    }
}

// ---------------- Pack weights: Wcat[k*D+d] = k<K ? Wroot[d,k] : Wrel[d,k-K] ----------------
__global__ void pack_w(const float* __restrict__ Wr, const float* __restrict__ We,
                       int K, int D, int dstoff) {
    int idx = blockIdx.x * blockDim.x + threadIdx.x;
    int tot = 2 * K * D;
    if (idx < tot) {
        int k = idx / D, d = idx - k * D;
        g_wcat[dstoff + idx] = (k < K) ? Wr[d * K + k] : We[d * K + (k - K)];
    }
}

// ---------------- Build [h | agg], scalar (K<=32) ----------------
__global__ void build_hcat_s(const float* __restrict__ h, int K) {
    int m = blockIdx.x;
    int c = threadIdx.x;
    if (c >= K) return;
    float own = h[(size_t)m * K + c];
    float s = 0.f;
    int e0 = g_off[m], e1 = g_off[m + 1];
    for (int e = e0; e < e1; e++)
        s += h[(size_t)g_rsrc[e] * K + c];
    size_t r = (size_t)m * (2 * K);
    g_hcat[r + c]     = own;
    g_hcat[r + K + c] = s;
}

// ---------------- Build [h | agg], vectorized float4 (K multiple of 4) ----------------
// One block per node; thread c handles 4 channels. NO in-degree cap: g_rsrc[e]
// is read directly (same address across the block -> hardware broadcast).
__global__ void build_hcat_v4(const float* __restrict__ h, int K) {
    int m = blockIdx.x;
    int c = threadIdx.x;            // 0 .. K/4-1
    int kq = K / 4;
    if (c >= kq) return;
    const float4* h4 = (const float4*)h;
    float4 own = h4[(size_t)m * kq + c];
    float4 s = make_float4(0.f, 0.f, 0.f, 0.f);
    int e0 = g_off[m], e1 = g_off[m + 1];
    for (int e = e0; e < e1; e++) {
        int srcn = g_rsrc[e];
        float4 v = h4[(size_t)srcn * kq + c];
        s.x += v.x; s.y += v.y; s.z += v.z; s.w += v.w;
    }
    float4* out4 = (float4*)g_hcat;
    size_t r = (size_t)m * (2 * kq);
    out4[r + c]      = own;
    out4[r + kq + c] = s;
}

// ---------------- Tiled SGEMM: C = A(MxK)*B(KxN) [+bias][relu], batched ----------------
template <int BM, int BN, int BK, int TM, int TN, bool RELU>
__global__ void __launch_bounds__((BM / TM) * (BN / TN))
gemm_kernel(const float* __restrict__ A, int lda, long sA,
            const float* __restrict__ Bm, int ldb, long sB,
            const float* __restrict__ bias,
            float* __restrict__ C, int ldc, long sC,
            int Kdim) {
    constexpr int THREADS = (BM / TM) * (BN / TN);
    __shared__ float As[BK][BM];
    __shared__ float Bs[BK][BN];
    const int tid = threadIdx.x;
    const float* Ab = A + (long)blockIdx.z * sA + (long)blockIdx.y * BM * lda;
    const float* Bb = Bm + (long)blockIdx.z * sB;
    const int n0 = blockIdx.x * BN;
    const int trow = tid / (BN / TN);
    const int tcol = tid % (BN / TN);
    float acc[TM][TN] = {};

    constexpr int A_ITems = BM * BK / 4;       // float4 loads
    constexpr int B_ITems = BK * BN / 4;
    constexpr int A_IT = (A_ITems + THREADS - 1) / THREADS;
    constexpr int B_IT = (B_ITems + THREADS - 1) / THREADS;

    for (int k0 = 0; k0 < Kdim; k0 += BK) {
#pragma unroll
        for (int it = 0; it < A_IT; it++) {
            int t = tid + it * THREADS;
            if (A_ITems % THREADS == 0 || t < A_ITems) {
                int r  = t / (BK / 4);
                int kc = (t % (BK / 4)) * 4;
                float4 v = *(const float4*)&Ab[(long)r * lda + k0 + kc];
                As[kc + 0][r] = v.x; As[kc + 1][r] = v.y;
                As[kc + 2][r] = v.z; As[kc + 3][r] = v.w;
            }
        }
#pragma unroll
        for (int it = 0; it < B_IT; it++) {
            int t = tid + it * THREADS;
            if (B_ITems % THREADS == 0 || t < B_ITems) {
                int r = t / (BN / 4);
                int c = (t % (BN / 4)) * 4;
                *(float4*)&Bs[r][c] = *(const float4*)&Bb[(long)(k0 + r) * ldb + n0 + c];
            }
        }
        __syncthreads();
#pragma unroll
        for (int k = 0; k < BK; k++) {
            float a[TM], bv[TN];
#pragma unroll
            for (int ii = 0; ii < TM; ii++) a[ii] = As[k][trow * TM + ii];
#pragma unroll
            for (int jj = 0; jj < TN; jj++) bv[jj] = Bs[k][tcol * TN + jj];
#pragma unroll
            for (int ii = 0; ii < TM; ii++)
#pragma unroll
                for (int jj = 0; jj < TN; jj++)
                    acc[ii][jj] += a[ii] * bv[jj];
        }
        __syncthreads();
    }

    float* Cb = C + (long)blockIdx.z * sC +
                ((long)blockIdx.y * BM + trow * TM) * ldc + n0 + tcol * TN;
#pragma unroll
    for (int ii = 0; ii < TM; ii++) {
#pragma unroll
        for (int jj = 0; jj < TN; jj++) {
            float v = acc[ii][jj];
            if (bias) v += bias[n0 + tcol * TN + jj];
            if (RELU) v = v > 0.f ? v : 0.f;
            Cb[(long)ii * ldc + jj] = v;
        }
    }
}

// ---------------- Transpose final features per batch: (1024x64) -> (64x1024) ----------------
__global__ void transpose_h(const float* __restrict__ H) {
    __shared__ float t[32][33];
    int b  = blockIdx.z;
    int i0 = blockIdx.x * 32, k0 = blockIdx.y * 32;
    int tx = threadIdx.x, ty = threadIdx.y;
#pragma unroll
    for (int y = 0; y < 32; y += 8)
        t[ty + y][tx] = H[((size_t)(b * NPTS + i0 + ty + y)) * 64 + k0 + tx];
    __syncthreads();
#pragma unroll
    for (int y = 0; y < 32; y += 8)
        g_Ht[((size_t)(b * 64 + k0 + ty + y)) * NPTS + i0 + tx] = t[tx][ty + y];
}

// ---------------- Launch ----------------
extern "C" void kernel_launch(void* const* d_in, const int* in_sizes, int n_in,
                              void* d_out, int out_size) {
    const float* x   = (const float*)d_in[0];
    const float* Wr0 = (const float*)d_in[1];
    const float* We0 = (const float*)d_in[2];
    const float* b0  = (const float*)d_in[3];
    const float* Wr1 = (const float*)d_in[4];
    const float* We1 = (const float*)d_in[5];
    const float* b1  = (const float*)d_in[6];
    const float* Wr2 = (const float*)d_in[7];
    const float* We2 = (const float*)d_in[8];
    const float* b2  = (const float*)d_in[9];
    const float* Wr3 = (const float*)d_in[10];
    const float* We3 = (const float*)d_in[11];
    const float* b3  = (const float*)d_in[12];
    float* out = (float*)d_out;

    float *hcat, *hbuf, *Ht, *wcat;
    cudaGetSymbolAddress((void**)&hcat, g_hcat);
    cudaGetSymbolAddress((void**)&hbuf, g_hbuf);
    cudaGetSymbolAddress((void**)&Ht,   g_Ht);
    cudaGetSymbolAddress((void**)&wcat, g_wcat);

    // 1) kNN graph
    knn_kernel<<<dim3(4, BATCH), 256>>>(x);

    // 2) reverse CSR
    zero_indeg<<<(NODES + 255) / 256, 256>>>();
    count_deg<<<(EDGES + 255) / 256, 256>>>();
    scan_kernel<<<1, 1024>>>();
    fill_rev<<<(EDGES + 255) / 256, 256>>>();

    // 3) pack weights
    pack_w<<<(2 * 16 * 128 + 255) / 256, 256>>>(Wr0, We0, 16, 128, WOFF0);
    pack_w<<<(2 * 128 * 256 + 255) / 256, 256>>>(Wr1, We1, 128, 256, WOFF1);
    pack_w<<<(2 * 256 * 256 + 255) / 256, 256>>>(Wr2, We2, 256, 256, WOFF2);
    pack_w<<<(2 * 256 * 64 + 255) / 256, 256>>>(Wr3, We3, 256, 64, WOFF3);

    // 4) layers
    // L0: K=16 -> D=128, relu
    build_hcat_s<<<NODES, 32>>>(x, 16);
    gemm_kernel<128, 128, 8, 8, 8, true><<<dim3(1, NODES / 128, 1), 256>>>(
        hcat, 32, 0, wcat + WOFF0, 128, 0, b0, hbuf, 128, 0, 32);
    // L1: 128 -> 256, relu
    build_hcat_v4<<<NODES, 32>>>(hbuf, 128);
    gemm_kernel<128, 128, 8, 8, 8, true><<<dim3(2, NODES / 128, 1), 256>>>(
        hcat, 256, 0, wcat + WOFF1, 256, 0, b1, hbuf, 256, 0, 256);
    // L2: 256 -> 256, relu
    build_hcat_v4<<<NODES, 64>>>(hbuf, 256);
    gemm_kernel<128, 128, 8, 8, 8, true><<<dim3(2, NODES / 128, 1), 256>>>(
        hcat, 512, 0, wcat + WOFF2, 256, 0, b2, hbuf, 256, 0, 512);
    // L3: 256 -> 64, no relu
    build_hcat_v4<<<NODES, 64>>>(hbuf, 256);
    gemm_kernel<128, 64, 8, 8, 4, false><<<dim3(1, NODES / 128, 1), 256>>>(
        hcat, 512, 0, wcat + WOFF3, 64, 0, b3, hbuf, 64, 0, 512);

    // 5) gram: out[b] = H_b (1024x64) * H_b^T
    transpose_h<<<dim3(32, 2, BATCH), dim3(32, 8)>>>(hbuf);
    gemm_kernel<128, 128, 8, 8, 8, false><<<dim3(8, 8, BATCH), 256>>>(
        hbuf, 64, (long)NPTS * 64,
        Ht, 1024, (long)64 * NPTS,
        nullptr,
        out, 1024, (long)NPTS * NPTS,
        64);
}

// round 5
// speedup vs baseline: 1.3798x; 1.3798x over previous
#include <cuda_runtime.h>
#include <cuda_bf16.h>
#include <math.h>
#include <stdint.h>

// ---------------- Problem constants ----------------
#define BATCH   16
#define NPTS    1024
#define CIN     16
#define NODES   (BATCH * NPTS)      // 16384
#define KNN     10
#define EDGES   (NODES * KNN)       // 163840

// packed weight offsets in bf16 hi/lo arrays, layout [N][Kpad] row-major
// L0: 128x64  L1: 256x256  L2: 256x512  L3: 64x512
#define WO0 0
#define WO1 8192
#define WO2 73728
#define WO3 204800
#define WTOT 237568

// ---------------- Device scratch ----------------
__device__ float          g_hbuf[NODES * 256];     // fp32 layer outputs
__device__ __nv_bfloat16  g_hcat_hi[NODES * 512];  // A operand hi
__device__ __nv_bfloat16  g_hcat_lo[NODES * 512];  // A operand lo
__device__ __nv_bfloat16  g_whi[WTOT];
__device__ __nv_bfloat16  g_wlo[WTOT];
__device__ __nv_bfloat16  g_Hhi[NODES * 64];       // final features for gram
__device__ __nv_bfloat16  g_Hlo[NODES * 64];
__device__ int g_nbr[EDGES];
__device__ int g_indeg[NODES];
__device__ int g_off[NODES + 1];
__device__ int g_cur[NODES];
__device__ int g_rsrc[EDGES];

// ---------------- PTX helpers (sm_80-era only, no arch-specific ISA) ----------------
__device__ __forceinline__ uint32_t smem_u32(const void* p) {
    uint32_t a;
    asm("{ .reg .u64 t; cvta.to.shared.u64 t, %1; cvt.u32.u64 %0, t; }" : "=r"(a) : "l"(p));
    return a;
}
__device__ __forceinline__ void ldsm_x4(uint32_t* r, uint32_t addr) {
    asm volatile("ldmatrix.sync.aligned.m8n8.x4.shared.b16 {%0,%1,%2,%3}, [%4];"
                 : "=r"(r[0]), "=r"(r[1]), "=r"(r[2]), "=r"(r[3]) : "r"(addr));
}
__device__ __forceinline__ void ldsm_x2(uint32_t* r, uint32_t addr) {
    asm volatile("ldmatrix.sync.aligned.m8n8.x2.shared.b16 {%0,%1}, [%2];"
                 : "=r"(r[0]), "=r"(r[1]) : "r"(addr));
}
__device__ __forceinline__ void mma_bf16(float* d, const uint32_t* a, const uint32_t* b) {
    asm volatile(
        "mma.sync.aligned.m16n8k16.row.col.f32.bf16.bf16.f32 "
        "{%0,%1,%2,%3}, {%4,%5,%6,%7}, {%8,%9}, {%0,%1,%2,%3};"
        : "+f"(d[0]), "+f"(d[1]), "+f"(d[2]), "+f"(d[3])
        : "r"(a[0]), "r"(a[1]), "r"(a[2]), "r"(a[3]), "r"(b[0]), "r"(b[1]));
}

// ---------------- kNN (fp32-exact, jax tie-break) ----------------
__global__ void knn_kernel(const float* __restrict__ x) {
    const int b   = blockIdx.y;
    const int tid = threadIdx.x;
    const int i   = blockIdx.x * 256 + tid;
    const float* xb = x + (size_t)b * NPTS * CIN;

    __shared__ float sx[256 * 16];
    __shared__ float ssq[256];
    __shared__ float sd[11][256];
    __shared__ int   si[11][256];

    float xi[16]; float sqi = 0.f;
#pragma unroll
    for (int c = 0; c < 16; c++) { xi[c] = xb[i * 16 + c]; sqi += xi[c] * xi[c]; }
#pragma unroll
    for (int t = 0; t < 11; t++) { sd[t][tid] = INFINITY; si[t][tid] = 0x7fffffff; }

    for (int jt = 0; jt < 4; jt++) {
        __syncthreads();
        float s = 0.f;
#pragma unroll
        for (int c = 0; c < 16; c++) {
            float v = xb[(jt * 256 + tid) * 16 + c];
            sx[tid * 16 + c] = v;
            s += v * v;
        }
        ssq[tid] = s;
        __syncthreads();
        for (int jj = 0; jj < 256; jj++) {
            float dot = 0.f;
#pragma unroll
            for (int c = 0; c < 16; c++) dot += xi[c] * sx[jj * 16 + c];
            float d2 = sqi + ssq[jj] - 2.0f * dot;
            int   j  = jt * 256 + jj;
            float wd = sd[10][tid]; int wi = si[10][tid];
            if (d2 < wd || (d2 == wd && j < wi)) {
                int t = 10;
                while (t > 0) {
                    float pd = sd[t - 1][tid]; int pi = si[t - 1][tid];
                    if (d2 < pd || (d2 == pd && j < pi)) {
                        sd[t][tid] = pd; si[t][tid] = pi; t--;
                    } else break;
                }
                sd[t][tid] = d2; si[t][tid] = j;
            }
        }
    }
    int g = b * NPTS + i;
#pragma unroll
    for (int t = 1; t <= 10; t++)
        g_nbr[g * KNN + (t - 1)] = b * NPTS + si[t][tid];
}

// ---------------- Reverse-CSR ----------------
__global__ void zero_indeg() {
    int idx = blockIdx.x * blockDim.x + threadIdx.x;
    if (idx < NODES) g_indeg[idx] = 0;
}
__global__ void count_deg() {
    int e = blockIdx.x * blockDim.x + threadIdx.x;
    if (e < EDGES) atomicAdd(&g_indeg[g_nbr[e]], 1);
}
__global__ void scan_kernel() {
    __shared__ int wsum[32];
    int tid = threadIdx.x, lane = tid & 31, w = tid >> 5;
    int base = tid * 16;
    int cnt[16]; int s = 0;
#pragma unroll
    for (int u = 0; u < 16; u++) { cnt[u] = g_indeg[base + u]; s += cnt[u]; }
    int incl = s;
#pragma unroll
    for (int o = 1; o < 32; o <<= 1) {
        int v = __shfl_up_sync(0xffffffffu, incl, o);
        if (lane >= o) incl += v;
    }
    if (lane == 31) wsum[w] = incl;
    __syncthreads();
    if (w == 0) {
        int t = wsum[lane];
#pragma unroll
        for (int o = 1; o < 32; o <<= 1) {
            int v = __shfl_up_sync(0xffffffffu, t, o);
            if (lane >= o) t += v;
        }
        wsum[lane] = t;
    }
    __syncthreads();
    int run = incl - s + (w ? wsum[w - 1] : 0);
#pragma unroll
    for (int u = 0; u < 16; u++) {
        g_off[base + u] = run;
        g_cur[base + u] = run;
        run += cnt[u];
    }
    if (tid == 1023) g_off[NODES] = run;
}
__global__ void fill_rev() {
    int e = blockIdx.x * blockDim.x + threadIdx.x;
    if (e < EDGES) {
        int m = g_nbr[e];
        int p = atomicAdd(&g_cur[m], 1);
        g_rsrc[p] = e / KNN;
    }
}

// ---------------- hi/lo split helpers ----------------
__device__ __forceinline__ void split1(float v, __nv_bfloat16& hi, __nv_bfloat16& lo) {
    hi = __float2bfloat16(v);
    lo = __float2bfloat16(v - __bfloat162float(hi));
}

// pack weights: row n of [N][Kpad] = [Wroot[n][0:K) | Wrel[n][0:K) | 0 pad]
__global__ void pack_split(const float* __restrict__ Wr, const float* __restrict__ We,
                           int K, int Kpad, int N, int off) {
    int idx = blockIdx.x * blockDim.x + threadIdx.x;
    int tot = N * Kpad;
    if (idx >= tot) return;
    int n = idx / Kpad, kk = idx - n * Kpad;
    float v = 0.f;
    if (kk < K) v = Wr[n * K + kk];
    else if (kk < 2 * K) v = We[n * K + kk - K];
    __nv_bfloat16 h, l; split1(v, h, l);
    g_whi[off + idx] = h; g_wlo[off + idx] = l;
}

__global__ void split_arr(const float* __restrict__ src, __nv_bfloat16* __restrict__ hi,
                          __nv_bfloat16* __restrict__ lo, int n) {
    int i = blockIdx.x * blockDim.x + threadIdx.x;
    if (i >= n) return;
    __nv_bfloat16 h, l; split1(src[i], h, l);
    hi[i] = h; lo[i] = l;
}

// L0 build: x (K=16) -> hcat rows of 64: [own16 | agg16 | zero32]
__global__ void build0(const float* __restrict__ x) {
    int m = blockIdx.x;
    int c = threadIdx.x;   // 0..63
    float v = 0.f;
    if (c < 16) v = x[(size_t)m * 16 + c];
    else if (c < 32) {
        int cc = c - 16; float s = 0.f;
        int e0 = g_off[m], e1 = g_off[m + 1];
        for (int e = e0; e < e1; e++) s += x[(size_t)g_rsrc[e] * 16 + cc];
        v = s;
    }
    __nv_bfloat16 h, l; split1(v, h, l);
    g_hcat_hi[(size_t)m * 64 + c] = h;
    g_hcat_lo[(size_t)m * 64 + c] = l;
}

// build [own | agg] rows of 2K from fp32 h (K = 128 or 256), split to bf16 hi/lo
template <int K>
__global__ void build_split(const float* __restrict__ h) {
    int m = blockIdx.x;
    int c = threadIdx.x;            // 0..K/4-1
    const int kq = K / 4;
    const float4* h4 = (const float4*)h;
    float4 own = h4[(size_t)m * kq + c];
    float4 s = make_float4(0.f, 0.f, 0.f, 0.f);
    int e0 = g_off[m], e1 = g_off[m + 1];
    for (int e = e0; e < e1; e++) {
        float4 v = h4[(size_t)g_rsrc[e] * kq + c];
        s.x += v.x; s.y += v.y; s.z += v.z; s.w += v.w;
    }
    size_t r = (size_t)m * (2 * K);
    const float* ov = &own.x;
    const float* sv = &s.x;
#pragma unroll
    for (int j = 0; j < 4; j++) {
        __nv_bfloat16 h1, l1; split1(ov[j], h1, l1);
        g_hcat_hi[r + c * 4 + j] = h1; g_hcat_lo[r + c * 4 + j] = l1;
        __nv_bfloat16 h2, l2; split1(sv[j], h2, l2);
        g_hcat_hi[r + K + c * 4 + j] = h2; g_hcat_lo[r + K + c * 4 + j] = l2;
    }
}

// ---------------- mma.sync bf16x3 GEMM ----------------
// C[z][m][n] = sum_k A[z][m][k] * B[z][n][k]  (+bias, +relu)
// A hi/lo rows at (z*saz + blockIdx.x*128 + r), lda = K
// B hi/lo rows at (z*sbz + blockIdx.y*BN + r), ldb = K
// C at z*scz + row*ldc + blockIdx.y*BN + col
// Block: 512 threads = 16 warps (4 M x 4 N). BM=128, BK=64.
template <int BN, bool RELU, bool BIAS>
__global__ void __launch_bounds__(512)
mma_gemm(const __nv_bfloat16* __restrict__ Ahi, const __nv_bfloat16* __restrict__ Alo,
         const __nv_bfloat16* __restrict__ Bhi, const __nv_bfloat16* __restrict__ Blo,
         const float* __restrict__ bias, float* __restrict__ C,
         int K, int ldc, long saz, long sbz, long scz) {
    extern __shared__ char smraw[];
    // 128B rows, 8x 16B chunks per row, XOR-swizzled
    char* Ah = smraw;                       // 128*128 = 16384 B
    char* Al = smraw + 16384;
    char* Bh = smraw + 32768;               // BN*128 B
    char* Bl = smraw + 32768 + BN * 128;

    const int tid = threadIdx.x;
    const int wid = tid >> 5, lane = tid & 31;
    const int wm = wid >> 2, wn = wid & 3;  // 4x4 warp grid
    constexpr int WN = BN / 4;              // warp N extent
    constexpr int NT = WN / 8;              // n8 tiles per warp

    const long  z     = blockIdx.z;
    const long  arow0 = z * saz + (long)blockIdx.x * 128;
    const long  brow0 = z * sbz + (long)blockIdx.y * BN;

    const uint32_t uAh = smem_u32(Ah), uAl = smem_u32(Al);
    const uint32_t uBh = smem_u32(Bh), uBl = smem_u32(Bl);

    float acc[2][NT][4];
#pragma unroll
    for (int i = 0; i < 2; i++)
#pragma unroll
        for (int j = 0; j < NT; j++)
#pragma unroll
            for (int q = 0; q < 4; q++) acc[i][j][q] = 0.f;

    const int nko = K >> 6;
    for (int ko = 0; ko < nko; ko++) {
        // ---- stage A(128x64) + B(BNx64), hi+lo, swizzled ----
        constexpr int CH = (128 + BN) * 8;      // 16B chunks per matrix
#pragma unroll
        for (int it = 0; it < CH / 512; it++) {
            int idx = tid + it * 512;
            int r = idx >> 3, c = idx & 7;
            int pc = c ^ (r & 7);
            if (r < 128) {
                size_t go = (size_t)(arow0 + r) * K + ko * 64 + c * 8;
                *(uint4*)(Ah + r * 128 + pc * 16) = *(const uint4*)(Ahi + go);
                *(uint4*)(Al + r * 128 + pc * 16) = *(const uint4*)(Alo + go);
            } else {
                int rb = r - 128;
                int prb = c ^ (rb & 7);
                size_t go = (size_t)(brow0 + rb) * K + ko * 64 + c * 8;
                *(uint4*)(Bh + rb * 128 + prb * 16) = *(const uint4*)(Bhi + go);
                *(uint4*)(Bl + rb * 128 + prb * 16) = *(const uint4*)(Blo + go);
            }
        }
        __syncthreads();

        // ---- compute: 4 k16 steps ----
#pragma unroll
        for (int k16 = 0; k16 < 4; k16++) {
            uint32_t afh[2][4], afl[2][4];
#pragma unroll
            for (int mt = 0; mt < 2; mt++) {
                int row = wm * 32 + mt * 16 + (lane & 15);
                int ch = (k16 * 2 + (lane >> 4)) ^ (row & 7);
                uint32_t off = (uint32_t)(row * 128 + ch * 16);
                ldsm_x4(afh[mt], uAh + off);
                ldsm_x4(afl[mt], uAl + off);
            }
            uint32_t bfh[NT][2], bfl[NT][2];
#pragma unroll
            for (int nt = 0; nt < NT; nt++) {
                int n = wn * WN + nt * 8 + (lane & 7);
                int ch = (k16 * 2 + ((lane >> 3) & 1)) ^ (n & 7);
                uint32_t off = (uint32_t)(n * 128 + ch * 16);
                ldsm_x2(bfh[nt], uBh + off);
                ldsm_x2(bfl[nt], uBl + off);
            }
#pragma unroll
            for (int mt = 0; mt < 2; mt++)
#pragma unroll
                for (int nt = 0; nt < NT; nt++) {
                    mma_bf16(acc[mt][nt], afh[mt], bfh[nt]);
                    mma_bf16(acc[mt][nt], afh[mt], bfl[nt]);
                    mma_bf16(acc[mt][nt], afl[mt], bfh[nt]);
                }
        }
        __syncthreads();
    }

    // ---- epilogue ----
    const long crow0 = (long)blockIdx.x * 128;
    const int  cn0   = blockIdx.y * BN;
#pragma unroll
    for (int mt = 0; mt < 2; mt++) {
        int r = wm * 32 + mt * 16 + (lane >> 2);
#pragma unroll
        for (int nt = 0; nt < NT; nt++) {
            int c = cn0 + wn * WN + nt * 8 + (lane & 3) * 2;
            float2 v0 = make_float2(acc[mt][nt][0], acc[mt][nt][1]);
            float2 v1 = make_float2(acc[mt][nt][2], acc[mt][nt][3]);
            if (BIAS) {
                float b0v = bias[c], b1v = bias[c + 1];
                v0.x += b0v; v0.y += b1v; v1.x += b0v; v1.y += b1v;
            }
            if (RELU) {
                v0.x = fmaxf(v0.x, 0.f); v0.y = fmaxf(v0.y, 0.f);
                v1.x = fmaxf(v1.x, 0.f); v1.y = fmaxf(v1.y, 0.f);
            }
            *(float2*)&C[z * scz + (crow0 + r) * ldc + c]       = v0;
            *(float2*)&C[z * scz + (crow0 + r + 8) * ldc + c]   = v1;
        }
    }
}

// ---------------- Launch ----------------
extern "C" void kernel_launch(void* const* d_in, const int* in_sizes, int n_in,
                              void* d_out, int out_size) {
    const float* x   = (const float*)d_in[0];
    const float* Wr0 = (const float*)d_in[1];
    const float* We0 = (const float*)d_in[2];
    const float* b0  = (const float*)d_in[3];
    const float* Wr1 = (const float*)d_in[4];
    const float* We1 = (const float*)d_in[5];
    const float* b1  = (const float*)d_in[6];
    const float* Wr2 = (const float*)d_in[7];
    const float* We2 = (const float*)d_in[8];
    const float* b2  = (const float*)d_in[9];
    const float* Wr3 = (const float*)d_in[10];
    const float* We3 = (const float*)d_in[11];
    const float* b3  = (const float*)d_in[12];
    float* out = (float*)d_out;

    float *hbuf;
    __nv_bfloat16 *ahi, *alo, *whi, *wlo, *Hhi, *Hlo;
    cudaGetSymbolAddress((void**)&hbuf, g_hbuf);
    cudaGetSymbolAddress((void**)&ahi,  g_hcat_hi);
    cudaGetSymbolAddress((void**)&alo,  g_hcat_lo);
    cudaGetSymbolAddress((void**)&whi,  g_whi);
    cudaGetSymbolAddress((void**)&wlo,  g_wlo);
    cudaGetSymbolAddress((void**)&Hhi,  g_Hhi);
    cudaGetSymbolAddress((void**)&Hlo,  g_Hlo);

    const int SZ128 = 32768 + 2 * 128 * 128;   // 65536
    const int SZ64  = 32768 + 2 * 64 * 128;    // 49152
    cudaFuncSetAttribute(mma_gemm<128, true, true>,   cudaFuncAttributeMaxDynamicSharedMemorySize, SZ128);
    cudaFuncSetAttribute(mma_gemm<128, false, false>, cudaFuncAttributeMaxDynamicSharedMemorySize, SZ128);
    cudaFuncSetAttribute(mma_gemm<64, false, true>,   cudaFuncAttributeMaxDynamicSharedMemorySize, SZ64);

    // 1) kNN graph
    knn_kernel<<<dim3(4, BATCH), 256>>>(x);

    // 2) reverse CSR
    zero_indeg<<<(NODES + 255) / 256, 256>>>();
    count_deg<<<(EDGES + 255) / 256, 256>>>();
    scan_kernel<<<1, 1024>>>();
    fill_rev<<<(EDGES + 255) / 256, 256>>>();

    // 3) pack weights (bf16 hi/lo, [N][Kpad])
    pack_split<<<(128 * 64 + 255) / 256, 256>>>(Wr0, We0, 16, 64, 128, WO0);
    pack_split<<<(256 * 256 + 255) / 256, 256>>>(Wr1, We1, 128, 256, 256, WO1);
    pack_split<<<(256 * 512 + 255) / 256, 256>>>(Wr2, We2, 256, 512, 256, WO2);
    pack_split<<<(64 * 512 + 255) / 256, 256>>>(Wr3, We3, 256, 512, 64, WO3);

    // 4) layers  (grid: x = M tiles, y = N tiles)
    build0<<<NODES, 64>>>(x);
    mma_gemm<128, true, true><<<dim3(128, 1, 1), 512, SZ128>>>(
        ahi, alo, whi + WO0, wlo + WO0, b0, hbuf, 64, 128, 0, 0, 0);
    build_split<128><<<NODES, 32>>>(hbuf);
    mma_gemm<128, true, true><<<dim3(128, 2, 1), 512, SZ128>>>(
        ahi, alo, whi + WO1, wlo + WO1, b1, hbuf, 256, 256, 0, 0, 0);
    build_split<256><<<NODES, 64>>>(hbuf);
    mma_gemm<128, true, true><<<dim3(128, 2, 1), 512, SZ128>>>(
        ahi, alo, whi + WO2, wlo + WO2, b2, hbuf, 512, 256, 0, 0, 0);
    build_split<256><<<NODES, 64>>>(hbuf);
    mma_gemm<64, false, true><<<dim3(128, 1, 1), 512, SZ64>>>(
        ahi, alo, whi + WO3, wlo + WO3, b3, hbuf, 512, 64, 0, 0, 0);

    // 5) gram: out[b] = H_b * H_b^T   (A = B = H, batched)
    split_arr<<<(NODES * 64 + 255) / 256, 256>>>(hbuf, Hhi, Hlo, NODES * 64);
    mma_gemm<128, false, false><<<dim3(8, 8, BATCH), 512, SZ128>>>(
        Hhi, Hlo, Hhi, Hlo, nullptr, out,
        64, NPTS, NPTS, NPTS, (long)NPTS * NPTS);
}

// round 6
// speedup vs baseline: 1.4997x; 1.0869x over previous
#include <cuda_runtime.h>
#include <cuda_bf16.h>
#include <math.h>
#include <stdint.h>

// ---------------- Problem constants ----------------
#define BATCH   16
#define NPTS    1024
#define CIN     16
#define NODES   (BATCH * NPTS)      // 16384
#define KNN     10
#define EDGES   (NODES * KNN)       // 163840

// packed weight offsets in bf16 hi/lo arrays, layout [N][Kpad] row-major
#define WO0 0
#define WO1 8192
#define WO2 73728
#define WO3 204800
#define WTOT 237568

// ---------------- Device scratch ----------------
__device__ float          g_hbuf[NODES * 256];
__device__ __nv_bfloat16  g_hcat_hi[NODES * 512];
__device__ __nv_bfloat16  g_hcat_lo[NODES * 512];
__device__ __nv_bfloat16  g_whi[WTOT];
__device__ __nv_bfloat16  g_wlo[WTOT];
__device__ __nv_bfloat16  g_Hhi[NODES * 64];
__device__ __nv_bfloat16  g_Hlo[NODES * 64];
__device__ int g_nbr[EDGES];
__device__ int g_indeg[NODES];
__device__ int g_off[NODES];
__device__ int g_cur[NODES];
__device__ int g_rsrc[EDGES];
__device__ int g_ctr;

// ---------------- PTX helpers (sm_80-era only) ----------------
__device__ __forceinline__ uint32_t smem_u32(const void* p) {
    uint32_t a;
    asm("{ .reg .u64 t; cvta.to.shared.u64 t, %1; cvt.u32.u64 %0, t; }" : "=r"(a) : "l"(p));
    return a;
}
__device__ __forceinline__ void ldsm_x4(uint32_t* r, uint32_t addr) {
    asm volatile("ldmatrix.sync.aligned.m8n8.x4.shared.b16 {%0,%1,%2,%3}, [%4];"
                 : "=r"(r[0]), "=r"(r[1]), "=r"(r[2]), "=r"(r[3]) : "r"(addr));
}
__device__ __forceinline__ void ldsm_x2(uint32_t* r, uint32_t addr) {
    asm volatile("ldmatrix.sync.aligned.m8n8.x2.shared.b16 {%0,%1}, [%2];"
                 : "=r"(r[0]), "=r"(r[1]) : "r"(addr));
}
__device__ __forceinline__ void mma_bf16(float* d, const uint32_t* a, const uint32_t* b) {
    asm volatile(
        "mma.sync.aligned.m16n8k16.row.col.f32.bf16.bf16.f32 "
        "{%0,%1,%2,%3}, {%4,%5,%6,%7}, {%8,%9}, {%0,%1,%2,%3};"
        : "+f"(d[0]), "+f"(d[1]), "+f"(d[2]), "+f"(d[3])
        : "r"(a[0]), "r"(a[1]), "r"(a[2]), "r"(a[3]), "r"(b[0]), "r"(b[1]));
}
__device__ __forceinline__ void cpa16(uint32_t s, const void* g) {
    asm volatile("cp.async.cg.shared.global [%0], [%1], 16;" :: "r"(s), "l"(g) : "memory");
}
__device__ __forceinline__ void cpa_commit() {
    asm volatile("cp.async.commit_group;" ::: "memory");
}

// ---------------- init: zero indeg + counter ----------------
__global__ void zero_indeg() {
    int idx = blockIdx.x * blockDim.x + threadIdx.x;
    if (idx < NODES) g_indeg[idx] = 0;
    if (idx == 0) g_ctr = 0;
}

// ---------------- fused weight pack (bf16 hi/lo split) ----------------
__device__ __forceinline__ void split1(float v, __nv_bfloat16& hi, __nv_bfloat16& lo) {
    hi = __float2bfloat16(v);
    lo = __float2bfloat16(v - __bfloat162float(hi));
}
__device__ __forceinline__ void pack_one(const float* Wr, const float* We,
                                         int K, int Kpad, int idx, int off) {
    int n = idx / Kpad, kk = idx - n * Kpad;
    float v = 0.f;
    if (kk < K) v = Wr[n * K + kk];
    else if (kk < 2 * K) v = We[n * K + kk - K];
    __nv_bfloat16 h, l; split1(v, h, l);
    g_whi[off + idx] = h; g_wlo[off + idx] = l;
}
// layers 0 (8192) + 1 (65536)
__global__ void pack_a(const float* __restrict__ Wr0, const float* __restrict__ We0,
                       const float* __restrict__ Wr1, const float* __restrict__ We1) {
    int idx = blockIdx.x * blockDim.x + threadIdx.x;
    if (idx < 8192) pack_one(Wr0, We0, 16, 64, idx, WO0);
    else if (idx < 8192 + 65536) pack_one(Wr1, We1, 128, 256, idx - 8192, WO1);
}
// layers 2 (131072) + 3 (32768)
__global__ void pack_b(const float* __restrict__ Wr2, const float* __restrict__ We2,
                       const float* __restrict__ Wr3, const float* __restrict__ We3) {
    int idx = blockIdx.x * blockDim.x + threadIdx.x;
    if (idx < 131072) pack_one(Wr2, We2, 256, 512, idx, WO2);
    else if (idx < 131072 + 32768) pack_one(Wr3, We3, 256, 512, idx - 131072, WO3);
}

// ---------------- kNN (fp32-exact, jax tie-break) + fused degree count ----------------
__global__ void knn_kernel(const float* __restrict__ x) {
    const int b   = blockIdx.y;
    const int tid = threadIdx.x;
    const int i   = blockIdx.x * 256 + tid;
    const float* xb = x + (size_t)b * NPTS * CIN;

    __shared__ float sx[256 * 16];
    __shared__ float ssq[256];
    __shared__ float sd[11][256];
    __shared__ int   si[11][256];

    float xi[16]; float sqi = 0.f;
#pragma unroll
    for (int c = 0; c < 16; c++) { xi[c] = xb[i * 16 + c]; sqi += xi[c] * xi[c]; }
#pragma unroll
    for (int t = 0; t < 11; t++) { sd[t][tid] = INFINITY; si[t][tid] = 0x7fffffff; }

    for (int jt = 0; jt < 4; jt++) {
        __syncthreads();
        float s = 0.f;
#pragma unroll
        for (int c = 0; c < 16; c++) {
            float v = xb[(jt * 256 + tid) * 16 + c];
            sx[tid * 16 + c] = v;
            s += v * v;
        }
        ssq[tid] = s;
        __syncthreads();
        for (int jj = 0; jj < 256; jj++) {
            float dot = 0.f;
#pragma unroll
            for (int c = 0; c < 16; c++) dot += xi[c] * sx[jj * 16 + c];
            float d2 = sqi + ssq[jj] - 2.0f * dot;
            int   j  = jt * 256 + jj;
            float wd = sd[10][tid]; int wi = si[10][tid];
            if (d2 < wd || (d2 == wd && j < wi)) {
                int t = 10;
                while (t > 0) {
                    float pd = sd[t - 1][tid]; int pi = si[t - 1][tid];
                    if (d2 < pd || (d2 == pd && j < pi)) {
                        sd[t][tid] = pd; si[t][tid] = pi; t--;
                    } else break;
                }
                sd[t][tid] = d2; si[t][tid] = j;
            }
        }
    }
    int g = b * NPTS + i;
#pragma unroll
    for (int t = 1; t <= 10; t++) {
        int nb = b * NPTS + si[t][tid];
        g_nbr[g * KNN + (t - 1)] = nb;
        atomicAdd(&g_indeg[nb], 1);
    }
}

// ---------------- atomic CSR range allocation (order-free, no scan) ----------------
__global__ void alloc_off() {
    int m = blockIdx.x * blockDim.x + threadIdx.x;
    if (m < NODES) {
        int d = g_indeg[m];
        int p = atomicAdd(&g_ctr, d);
        g_off[m] = p;
        g_cur[m] = p;
    }
}
__global__ void fill_rev() {
    int e = blockIdx.x * blockDim.x + threadIdx.x;
    if (e < EDGES) {
        int m = g_nbr[e];
        int p = atomicAdd(&g_cur[m], 1);
        g_rsrc[p] = e / KNN;
    }
}

// ---------------- build [own | agg] ----------------
// L0: x (K=16) -> rows of 64: [own16 | agg16 | zero32]
__global__ void build0(const float* __restrict__ x) {
    int m = blockIdx.x;
    int c = threadIdx.x;   // 0..63
    float v = 0.f;
    if (c < 16) v = x[(size_t)m * 16 + c];
    else if (c < 32) {
        int cc = c - 16; float s = 0.f;
        int e0 = g_off[m], e1 = e0 + g_indeg[m];
        for (int e = e0; e < e1; e++) s += x[(size_t)g_rsrc[e] * 16 + cc];
        v = s;
    }
    __nv_bfloat16 h, l; split1(v, h, l);
    g_hcat_hi[(size_t)m * 64 + c] = h;
    g_hcat_lo[(size_t)m * 64 + c] = l;
}
template <int K>
__global__ void build_split(const float* __restrict__ h) {
    int m = blockIdx.x;
    int c = threadIdx.x;            // 0..K/4-1
    const int kq = K / 4;
    const float4* h4 = (const float4*)h;
    float4 own = h4[(size_t)m * kq + c];
    float4 s = make_float4(0.f, 0.f, 0.f, 0.f);
    int e0 = g_off[m], e1 = e0 + g_indeg[m];
    for (int e = e0; e < e1; e++) {
        float4 v = h4[(size_t)g_rsrc[e] * kq + c];
        s.x += v.x; s.y += v.y; s.z += v.z; s.w += v.w;
    }
    size_t r = (size_t)m * (2 * K);
    const float* ov = &own.x;
    const float* sv = &s.x;
#pragma unroll
    for (int j = 0; j < 4; j++) {
        __nv_bfloat16 h1, l1; split1(ov[j], h1, l1);
        g_hcat_hi[r + c * 4 + j] = h1; g_hcat_lo[r + c * 4 + j] = l1;
        __nv_bfloat16 h2, l2; split1(sv[j], h2, l2);
        g_hcat_hi[r + K + c * 4 + j] = h2; g_hcat_lo[r + K + c * 4 + j] = l2;
    }
}

// ---------------- mma.sync bf16x3 GEMM, cp.async double-buffered ----------------
// C[z][m][n] = sum_k A[z][m][k] * B[z][n][k]  (+bias, +relu)
// SPLITOUT: write bf16 hi/lo pairs to Ohi/Olo (ldc = N) instead of fp32 C.
// Block: 512 threads = 16 warps (4 M x 4 N). BM=128, BK=64.
template <int BN, bool RELU, bool BIAS, bool SPLITOUT>
__global__ void __launch_bounds__(512)
mma_gemm(const __nv_bfloat16* __restrict__ Ahi, const __nv_bfloat16* __restrict__ Alo,
         const __nv_bfloat16* __restrict__ Bhi, const __nv_bfloat16* __restrict__ Blo,
         const float* __restrict__ bias, float* __restrict__ C,
         __nv_bfloat16* __restrict__ Ohi, __nv_bfloat16* __restrict__ Olo,
         int K, int ldc, long saz, long sbz, long scz) {
    extern __shared__ char smraw[];
    constexpr int OFF_AL = 16384;                 // A: 128 rows x 128B
    constexpr int OFF_BH = 32768;
    constexpr int OFF_BL = 32768 + BN * 128;
    constexpr int STAGE  = 32768 + 2 * BN * 128;  // bytes per stage

    const int tid = threadIdx.x;
    const int wid = tid >> 5, lane = tid & 31;
    const int wm = wid >> 2, wn = wid & 3;
    constexpr int WN = BN / 4;
    constexpr int NT = WN / 8;

    const long z     = blockIdx.z;
    const long arow0 = z * saz + (long)blockIdx.x * 128;
    const long brow0 = z * sbz + (long)blockIdx.y * BN;

    const uint32_t uSm = smem_u32(smraw);

    float acc[2][NT][4];
#pragma unroll
    for (int i = 0; i < 2; i++)
#pragma unroll
        for (int j = 0; j < NT; j++)
#pragma unroll
            for (int q = 0; q < 4; q++) acc[i][j][q] = 0.f;

    const int nko = K >> 6;
    constexpr int CH = (128 + BN) * 8;   // 16B chunks per operand pair

    auto stage = [&](int ko, int buf) {
        const uint32_t base = uSm + buf * STAGE;
#pragma unroll
        for (int it = 0; it < CH / 512; it++) {
            int idx = tid + it * 512;
            int r = idx >> 3, c = idx & 7;
            if (r < 128) {
                int pc = c ^ (r & 7);
                size_t go = (size_t)(arow0 + r) * K + ko * 64 + c * 8;
                cpa16(base + r * 128 + pc * 16, Ahi + go);
                cpa16(base + OFF_AL + r * 128 + pc * 16, Alo + go);
            } else {
                int rb = r - 128, prb = c ^ (rb & 7);
                size_t go = (size_t)(brow0 + rb) * K + ko * 64 + c * 8;
                cpa16(base + OFF_BH + rb * 128 + prb * 16, Bhi + go);
                cpa16(base + OFF_BL + rb * 128 + prb * 16, Blo + go);
            }
        }
        cpa_commit();
    };

    stage(0, 0);
    for (int ko = 0; ko < nko; ko++) {
        if (ko + 1 < nko) {
            stage(ko + 1, (ko + 1) & 1);
            asm volatile("cp.async.wait_group 1;" ::: "memory");
        } else {
            asm volatile("cp.async.wait_group 0;" ::: "memory");
        }
        __syncthreads();

        const uint32_t base = uSm + (ko & 1) * STAGE;
        const uint32_t uAh = base, uAl = base + OFF_AL;
        const uint32_t uBh = base + OFF_BH, uBl = base + OFF_BL;
#pragma unroll
        for (int k16 = 0; k16 < 4; k16++) {
            uint32_t afh[2][4], afl[2][4];
#pragma unroll
            for (int mt = 0; mt < 2; mt++) {
                int row = wm * 32 + mt * 16 + (lane & 15);
                int ch = (k16 * 2 + (lane >> 4)) ^ (row & 7);
                uint32_t off = (uint32_t)(row * 128 + ch * 16);
                ldsm_x4(afh[mt], uAh + off);
                ldsm_x4(afl[mt], uAl + off);
            }
            uint32_t bfh[NT][2], bfl[NT][2];
#pragma unroll
            for (int nt = 0; nt < NT; nt++) {
                int n = wn * WN + nt * 8 + (lane & 7);
                int ch = (k16 * 2 + ((lane >> 3) & 1)) ^ (n & 7);
                uint32_t off = (uint32_t)(n * 128 + ch * 16);
                ldsm_x2(bfh[nt], uBh + off);
                ldsm_x2(bfl[nt], uBl + off);
            }
#pragma unroll
            for (int mt = 0; mt < 2; mt++)
#pragma unroll
                for (int nt = 0; nt < NT; nt++) {
                    mma_bf16(acc[mt][nt], afh[mt], bfh[nt]);
                    mma_bf16(acc[mt][nt], afh[mt], bfl[nt]);
                    mma_bf16(acc[mt][nt], afl[mt], bfh[nt]);
                }
        }
        __syncthreads();
    }

    // ---- epilogue ----
    const long crow0 = (long)blockIdx.x * 128;
    const int  cn0   = blockIdx.y * BN;
#pragma unroll
    for (int mt = 0; mt < 2; mt++) {
        int r = wm * 32 + mt * 16 + (lane >> 2);
#pragma unroll
        for (int nt = 0; nt < NT; nt++) {
            int c = cn0 + wn * WN + nt * 8 + (lane & 3) * 2;
            float2 v0 = make_float2(acc[mt][nt][0], acc[mt][nt][1]);
            float2 v1 = make_float2(acc[mt][nt][2], acc[mt][nt][3]);
            if (BIAS) {
                float b0v = bias[c], b1v = bias[c + 1];
                v0.x += b0v; v0.y += b1v; v1.x += b0v; v1.y += b1v;
            }
            if (RELU) {
                v0.x = fmaxf(v0.x, 0.f); v0.y = fmaxf(v0.y, 0.f);
                v1.x = fmaxf(v1.x, 0.f); v1.y = fmaxf(v1.y, 0.f);
            }
            if (SPLITOUT) {
                __nv_bfloat16 h0, l0, h1, l1, h2, l2, h3, l3;
                split1(v0.x, h0, l0); split1(v0.y, h1, l1);
                split1(v1.x, h2, l2); split1(v1.y, h3, l3);
                size_t o0 = (size_t)(crow0 + r) * ldc + c;
                size_t o1 = (size_t)(crow0 + r + 8) * ldc + c;
                __nv_bfloat162 t;
                t.x = h0; t.y = h1; *(__nv_bfloat162*)&Ohi[o0] = t;
                t.x = l0; t.y = l1; *(__nv_bfloat162*)&Olo[o0] = t;
                t.x = h2; t.y = h3; *(__nv_bfloat162*)&Ohi[o1] = t;
                t.x = l2; t.y = l3; *(__nv_bfloat162*)&Olo[o1] = t;
            } else {
                *(float2*)&C[z * scz + (crow0 + r) * ldc + c]     = v0;
                *(float2*)&C[z * scz + (crow0 + r + 8) * ldc + c] = v1;
            }
        }
    }
}

// ---------------- Launch ----------------
extern "C" void kernel_launch(void* const* d_in, const int* in_sizes, int n_in,
                              void* d_out, int out_size) {
    const float* x   = (const float*)d_in[0];
    const float* Wr0 = (const float*)d_in[1];
    const float* We0 = (const float*)d_in[2];
    const float* b0  = (const float*)d_in[3];
    const float* Wr1 = (const float*)d_in[4];
    const float* We1 = (const float*)d_in[5];
    const float* b1  = (const float*)d_in[6];
    const float* Wr2 = (const float*)d_in[7];
    const float* We2 = (const float*)d_in[8];
    const float* b2  = (const float*)d_in[9];
    const float* Wr3 = (const float*)d_in[10];
    const float* We3 = (const float*)d_in[11];
    const float* b3  = (const float*)d_in[12];
    float* out = (float*)d_out;

    float *hbuf;
    __nv_bfloat16 *ahi, *alo, *whi, *wlo, *Hhi, *Hlo;
    cudaGetSymbolAddress((void**)&hbuf, g_hbuf);
    cudaGetSymbolAddress((void**)&ahi,  g_hcat_hi);
    cudaGetSymbolAddress((void**)&alo,  g_hcat_lo);
    cudaGetSymbolAddress((void**)&whi,  g_whi);
    cudaGetSymbolAddress((void**)&wlo,  g_wlo);
    cudaGetSymbolAddress((void**)&Hhi,  g_Hhi);
    cudaGetSymbolAddress((void**)&Hlo,  g_Hlo);

    const int SZ128 = 2 * (32768 + 2 * 128 * 128);  // 131072 (double-buffered)
    const int SZ64  = 2 * (32768 + 2 * 64 * 128);   // 98304
    cudaFuncSetAttribute(mma_gemm<128, true, true, false>,   cudaFuncAttributeMaxDynamicSharedMemorySize, SZ128);
    cudaFuncSetAttribute(mma_gemm<64, false, true, true>,    cudaFuncAttributeMaxDynamicSharedMemorySize, SZ64);
    cudaFuncSetAttribute(mma_gemm<128, false, false, false>, cudaFuncAttributeMaxDynamicSharedMemorySize, SZ128);

    // launch order puts knn 4th (ncu capture position)
    zero_indeg<<<(NODES + 255) / 256, 256>>>();
    pack_a<<<(8192 + 65536 + 255) / 256, 256>>>(Wr0, We0, Wr1, We1);
    pack_b<<<(131072 + 32768 + 255) / 256, 256>>>(Wr2, We2, Wr3, We3);
    knn_kernel<<<dim3(4, BATCH), 256>>>(x);
    alloc_off<<<(NODES + 255) / 256, 256>>>();
    fill_rev<<<(EDGES + 255) / 256, 256>>>();

    // layers
    build0<<<NODES, 64>>>(x);
    mma_gemm<128, true, true, false><<<dim3(128, 1, 1), 512, SZ128>>>(
        ahi, alo, whi + WO0, wlo + WO0, b0, hbuf, nullptr, nullptr, 64, 128, 0, 0, 0);
    build_split<128><<<NODES, 32>>>(hbuf);
    mma_gemm<128, true, true, false><<<dim3(128, 2, 1), 512, SZ128>>>(
        ahi, alo, whi + WO1, wlo + WO1, b1, hbuf, nullptr, nullptr, 256, 256, 0, 0, 0);
    build_split<256><<<NODES, 64>>>(hbuf);
    mma_gemm<128, true, true, false><<<dim3(128, 2, 1), 512, SZ128>>>(
        ahi, alo, whi + WO2, wlo + WO2, b2, hbuf, nullptr, nullptr, 512, 256, 0, 0, 0);
    build_split<256><<<NODES, 64>>>(hbuf);
    // L3 writes bf16 hi/lo directly for gram (no fp32 pass, no split_arr)
    mma_gemm<64, false, true, true><<<dim3(128, 1, 1), 512, SZ64>>>(
        ahi, alo, whi + WO3, wlo + WO3, b3, nullptr, Hhi, Hlo, 512, 64, 0, 0, 0);

    // gram: out[b] = H_b * H_b^T
    mma_gemm<128, false, false, false><<<dim3(8, 8, BATCH), 512, SZ128>>>(
        Hhi, Hlo, Hhi, Hlo, nullptr, out, nullptr, nullptr,
        64, NPTS, NPTS, NPTS, (long)NPTS * NPTS);
}

// round 7
// speedup vs baseline: 2.2598x; 1.5068x over previous
#include <cuda_runtime.h>
#include <cuda_bf16.h>
#include <math.h>
#include <stdint.h>

// ---------------- Problem constants ----------------
#define BATCH   16
#define NPTS    1024
#define CIN     16
#define NODES   (BATCH * NPTS)      // 16384
#define KNN     10
#define EDGES   (NODES * KNN)       // 163840
#define JCHUNK  4                   // candidate-axis partitions

// packed weight offsets in bf16 hi/lo arrays, layout [N][Kpad] row-major
#define WO0 0
#define WO1 8192
#define WO2 73728
#define WO3 204800
#define WTOT 237568

// ---------------- Device scratch ----------------
__device__ float          g_hbuf[NODES * 256];
__device__ __nv_bfloat16  g_hcat_hi[NODES * 512];
__device__ __nv_bfloat16  g_hcat_lo[NODES * 512];
__device__ __nv_bfloat16  g_whi[WTOT];
__device__ __nv_bfloat16  g_wlo[WTOT];
__device__ __nv_bfloat16  g_Hhi[NODES * 64];
__device__ __nv_bfloat16  g_Hlo[NODES * 64];
__device__ float g_pd[NODES * JCHUNK * 11];   // partial top-11 distances
__device__ int   g_pi[NODES * JCHUNK * 11];   // partial top-11 indices (batch-local)
__device__ int g_nbr[EDGES];
__device__ int g_indeg[NODES];
__device__ int g_off[NODES];
__device__ int g_cur[NODES];
__device__ int g_rsrc[EDGES];
__device__ int g_ctr;

// ---------------- PTX helpers (sm_80-era only) ----------------
__device__ __forceinline__ uint32_t smem_u32(const void* p) {
    uint32_t a;
    asm("{ .reg .u64 t; cvta.to.shared.u64 t, %1; cvt.u32.u64 %0, t; }" : "=r"(a) : "l"(p));
    return a;
}
__device__ __forceinline__ void ldsm_x4(uint32_t* r, uint32_t addr) {
    asm volatile("ldmatrix.sync.aligned.m8n8.x4.shared.b16 {%0,%1,%2,%3}, [%4];"
                 : "=r"(r[0]), "=r"(r[1]), "=r"(r[2]), "=r"(r[3]) : "r"(addr));
}
__device__ __forceinline__ void ldsm_x2(uint32_t* r, uint32_t addr) {
    asm volatile("ldmatrix.sync.aligned.m8n8.x2.shared.b16 {%0,%1}, [%2];"
                 : "=r"(r[0]), "=r"(r[1]) : "r"(addr));
}
__device__ __forceinline__ void mma_bf16(float* d, const uint32_t* a, const uint32_t* b) {
    asm volatile(
        "mma.sync.aligned.m16n8k16.row.col.f32.bf16.bf16.f32 "
        "{%0,%1,%2,%3}, {%4,%5,%6,%7}, {%8,%9}, {%0,%1,%2,%3};"
        : "+f"(d[0]), "+f"(d[1]), "+f"(d[2]), "+f"(d[3])
        : "r"(a[0]), "r"(a[1]), "r"(a[2]), "r"(a[3]), "r"(b[0]), "r"(b[1]));
}
__device__ __forceinline__ void cpa16(uint32_t s, const void* g) {
    asm volatile("cp.async.cg.shared.global [%0], [%1], 16;" :: "r"(s), "l"(g) : "memory");
}
__device__ __forceinline__ void cpa_commit() {
    asm volatile("cp.async.commit_group;" ::: "memory");
}

// ---------------- init ----------------
__global__ void zero_indeg() {
    int idx = blockIdx.x * blockDim.x + threadIdx.x;
    if (idx < NODES) g_indeg[idx] = 0;
    if (idx == 0) g_ctr = 0;
}

// ---------------- fused weight pack (bf16 hi/lo split) ----------------
__device__ __forceinline__ void split1(float v, __nv_bfloat16& hi, __nv_bfloat16& lo) {
    hi = __float2bfloat16(v);
    lo = __float2bfloat16(v - __bfloat162float(hi));
}
__device__ __forceinline__ void pack_one(const float* Wr, const float* We,
                                         int K, int Kpad, int idx, int off) {
    int n = idx / Kpad, kk = idx - n * Kpad;
    float v = 0.f;
    if (kk < K) v = Wr[n * K + kk];
    else if (kk < 2 * K) v = We[n * K + kk - K];
    __nv_bfloat16 h, l; split1(v, h, l);
    g_whi[off + idx] = h; g_wlo[off + idx] = l;
}
__global__ void pack_a(const float* __restrict__ Wr0, const float* __restrict__ We0,
                       const float* __restrict__ Wr1, const float* __restrict__ We1) {
    int idx = blockIdx.x * blockDim.x + threadIdx.x;
    if (idx < 8192) pack_one(Wr0, We0, 16, 64, idx, WO0);
    else if (idx < 8192 + 65536) pack_one(Wr1, We1, 128, 256, idx - 8192, WO1);
}
__global__ void pack_b(const float* __restrict__ Wr2, const float* __restrict__ We2,
                       const float* __restrict__ Wr3, const float* __restrict__ We3) {
    int idx = blockIdx.x * blockDim.x + threadIdx.x;
    if (idx < 131072) pack_one(Wr2, We2, 256, 512, idx, WO2);
    else if (idx < 131072 + 32768) pack_one(Wr3, We3, 256, 512, idx - 131072, WO3);
}

// ---------------- sorted insert (register-resident, unrolled) ----------------
#define TRY_INSERT(sd, si, d2, j) do {                                             \
    if ((d2) < sd[10] || ((d2) == sd[10] && (j) < si[10])) {                       \
        sd[10] = (d2); si[10] = (j);                                               \
        _Pragma("unroll")                                                          \
        for (int _t = 10; _t > 0; _t--) {                                          \
            bool _sw = sd[_t] < sd[_t-1] || (sd[_t] == sd[_t-1] && si[_t] < si[_t-1]); \
            float _da = sd[_t], _db = sd[_t-1];                                    \
            int   _ia = si[_t], _ib = si[_t-1];                                    \
            sd[_t-1] = _sw ? _da : _db; si[_t-1] = _sw ? _ia : _ib;                \
            sd[_t]   = _sw ? _db : _da; si[_t]   = _sw ? _ib : _ia;                \
        }                                                                          \
    }                                                                              \
} while (0)

// ---------------- kNN phase 1: partial top-11 over a 256-candidate chunk ----------------
// grid (4 ichunks, JCHUNK jchunks, BATCH), block 256
__global__ void knn_part(const float* __restrict__ x) {
    const int b   = blockIdx.z;
    const int tid = threadIdx.x;
    const int i   = blockIdx.x * 256 + tid;
    const int j0  = blockIdx.y * 256;
    const float* xb = x + (size_t)b * NPTS * CIN;

    __shared__ float sx[256 * 16];
    __shared__ float ssq[256];

    float xi[16]; float sqi = 0.f;
#pragma unroll
    for (int c = 0; c < 16; c++) { xi[c] = xb[i * 16 + c]; sqi += xi[c] * xi[c]; }

    // stage candidate tile
    {
        float s = 0.f;
#pragma unroll
        for (int c = 0; c < 16; c++) {
            float v = xb[(j0 + tid) * 16 + c];
            sx[tid * 16 + c] = v;
            s += v * v;
        }
        ssq[tid] = s;
    }
    __syncthreads();

    float sd[11]; int si[11];
#pragma unroll
    for (int t = 0; t < 11; t++) { sd[t] = INFINITY; si[t] = 0x7fffffff; }

    for (int jj = 0; jj < 256; jj++) {
        float dot = 0.f;
#pragma unroll
        for (int c = 0; c < 16; c++) dot += xi[c] * sx[jj * 16 + c];
        float d2 = sqi + ssq[jj] - 2.0f * dot;
        int   j  = j0 + jj;
        TRY_INSERT(sd, si, d2, j);
    }

    const size_t base = ((size_t)(b * NPTS + i) * JCHUNK + blockIdx.y) * 11;
#pragma unroll
    for (int t = 0; t < 11; t++) { g_pd[base + t] = sd[t]; g_pi[base + t] = si[t]; }
}

// ---------------- kNN phase 2: merge JCHUNK sorted 11-lists, emit neighbors ----------------
__global__ void knn_merge() {
    int g = blockIdx.x * blockDim.x + threadIdx.x;
    if (g >= NODES) return;
    const size_t base = (size_t)g * JCHUNK * 11;

    float sd[11]; int si[11];
#pragma unroll
    for (int t = 0; t < 11; t++) { sd[t] = g_pd[base + t]; si[t] = g_pi[base + t]; }
#pragma unroll
    for (int q = 1; q < JCHUNK; q++) {
#pragma unroll
        for (int u = 0; u < 11; u++) {
            float d2 = g_pd[base + q * 11 + u];
            int   j  = g_pi[base + q * 11 + u];
            TRY_INSERT(sd, si, d2, j);
        }
    }
    int boff = (g / NPTS) * NPTS;
#pragma unroll
    for (int t = 1; t <= 10; t++) {
        int nb = boff + si[t];
        g_nbr[g * KNN + (t - 1)] = nb;
        atomicAdd(&g_indeg[nb], 1);
    }
}

// ---------------- atomic CSR range allocation ----------------
__global__ void alloc_off() {
    int m = blockIdx.x * blockDim.x + threadIdx.x;
    if (m < NODES) {
        int d = g_indeg[m];
        int p = atomicAdd(&g_ctr, d);
        g_off[m] = p;
        g_cur[m] = p;
    }
}
__global__ void fill_rev() {
    int e = blockIdx.x * blockDim.x + threadIdx.x;
    if (e < EDGES) {
        int m = g_nbr[e];
        int p = atomicAdd(&g_cur[m], 1);
        g_rsrc[p] = e / KNN;
    }
}

// ---------------- build [own | agg] ----------------
__global__ void build0(const float* __restrict__ x) {
    int m = blockIdx.x;
    int c = threadIdx.x;   // 0..63
    float v = 0.f;
    if (c < 16) v = x[(size_t)m * 16 + c];
    else if (c < 32) {
        int cc = c - 16; float s = 0.f;
        int e0 = g_off[m], e1 = e0 + g_indeg[m];
        for (int e = e0; e < e1; e++) s += x[(size_t)g_rsrc[e] * 16 + cc];
        v = s;
    }
    __nv_bfloat16 h, l; split1(v, h, l);
    g_hcat_hi[(size_t)m * 64 + c] = h;
    g_hcat_lo[(size_t)m * 64 + c] = l;
}
template <int K>
__global__ void build_split(const float* __restrict__ h) {
    int m = blockIdx.x;
    int c = threadIdx.x;            // 0..K/4-1
    const int kq = K / 4;
    const float4* h4 = (const float4*)h;
    float4 own = h4[(size_t)m * kq + c];
    float4 s = make_float4(0.f, 0.f, 0.f, 0.f);
    int e0 = g_off[m], e1 = e0 + g_indeg[m];
    for (int e = e0; e < e1; e++) {
        float4 v = h4[(size_t)g_rsrc[e] * kq + c];
        s.x += v.x; s.y += v.y; s.z += v.z; s.w += v.w;
    }
    size_t r = (size_t)m * (2 * K);
    const float* ov = &own.x;
    const float* sv = &s.x;
#pragma unroll
    for (int j = 0; j < 4; j++) {
        __nv_bfloat16 h1, l1; split1(ov[j], h1, l1);
        g_hcat_hi[r + c * 4 + j] = h1; g_hcat_lo[r + c * 4 + j] = l1;
        __nv_bfloat16 h2, l2; split1(sv[j], h2, l2);
        g_hcat_hi[r + K + c * 4 + j] = h2; g_hcat_lo[r + K + c * 4 + j] = l2;
    }
}

// ---------------- mma.sync bf16x3 GEMM, cp.async double-buffered ----------------
template <int BN, bool RELU, bool BIAS, bool SPLITOUT>
__global__ void __launch_bounds__(512)
mma_gemm(const __nv_bfloat16* __restrict__ Ahi, const __nv_bfloat16* __restrict__ Alo,
         const __nv_bfloat16* __restrict__ Bhi, const __nv_bfloat16* __restrict__ Blo,
         const float* __restrict__ bias, float* __restrict__ C,
         __nv_bfloat16* __restrict__ Ohi, __nv_bfloat16* __restrict__ Olo,
         int K, int ldc, long saz, long sbz, long scz) {
    extern __shared__ char smraw[];
    constexpr int OFF_AL = 16384;
    constexpr int OFF_BH = 32768;
    constexpr int OFF_BL = 32768 + BN * 128;
    constexpr int STAGE  = 32768 + 2 * BN * 128;

    const int tid = threadIdx.x;
    const int wid = tid >> 5, lane = tid & 31;
    const int wm = wid >> 2, wn = wid & 3;
    constexpr int WN = BN / 4;
    constexpr int NT = WN / 8;

    const long z     = blockIdx.z;
    const long arow0 = z * saz + (long)blockIdx.x * 128;
    const long brow0 = z * sbz + (long)blockIdx.y * BN;

    const uint32_t uSm = smem_u32(smraw);

    float acc[2][NT][4];
#pragma unroll
    for (int i = 0; i < 2; i++)
#pragma unroll
        for (int j = 0; j < NT; j++)
#pragma unroll
            for (int q = 0; q < 4; q++) acc[i][j][q] = 0.f;

    const int nko = K >> 6;
    constexpr int CH = (128 + BN) * 8;

    auto stage = [&](int ko, int buf) {
        const uint32_t base = uSm + buf * STAGE;
#pragma unroll
        for (int it = 0; it < CH / 512; it++) {
            int idx = tid + it * 512;
            int r = idx >> 3, c = idx & 7;
            if (r < 128) {
                int pc = c ^ (r & 7);
                size_t go = (size_t)(arow0 + r) * K + ko * 64 + c * 8;
                cpa16(base + r * 128 + pc * 16, Ahi + go);
                cpa16(base + OFF_AL + r * 128 + pc * 16, Alo + go);
            } else {
                int rb = r - 128, prb = c ^ (rb & 7);
                size_t go = (size_t)(brow0 + rb) * K + ko * 64 + c * 8;
                cpa16(base + OFF_BH + rb * 128 + prb * 16, Bhi + go);
                cpa16(base + OFF_BL + rb * 128 + prb * 16, Blo + go);
            }
        }
        cpa_commit();
    };

    stage(0, 0);
    for (int ko = 0; ko < nko; ko++) {
        if (ko + 1 < nko) {
            stage(ko + 1, (ko + 1) & 1);
            asm volatile("cp.async.wait_group 1;" ::: "memory");
        } else {
            asm volatile("cp.async.wait_group 0;" ::: "memory");
        }
        __syncthreads();

        const uint32_t base = uSm + (ko & 1) * STAGE;
        const uint32_t uAh = base, uAl = base + OFF_AL;
        const uint32_t uBh = base + OFF_BH, uBl = base + OFF_BL;
#pragma unroll
        for (int k16 = 0; k16 < 4; k16++) {
            uint32_t afh[2][4], afl[2][4];
#pragma unroll
            for (int mt = 0; mt < 2; mt++) {
                int row = wm * 32 + mt * 16 + (lane & 15);
                int ch = (k16 * 2 + (lane >> 4)) ^ (row & 7);
                uint32_t off = (uint32_t)(row * 128 + ch * 16);
                ldsm_x4(afh[mt], uAh + off);
                ldsm_x4(afl[mt], uAl + off);
            }
            uint32_t bfh[NT][2], bfl[NT][2];
#pragma unroll
            for (int nt = 0; nt < NT; nt++) {
                int n = wn * WN + nt * 8 + (lane & 7);
                int ch = (k16 * 2 + ((lane >> 3) & 1)) ^ (n & 7);
                uint32_t off = (uint32_t)(n * 128 + ch * 16);
                ldsm_x2(bfh[nt], uBh + off);
                ldsm_x2(bfl[nt], uBl + off);
            }
#pragma unroll
            for (int mt = 0; mt < 2; mt++)
#pragma unroll
                for (int nt = 0; nt < NT; nt++) {
                    mma_bf16(acc[mt][nt], afh[mt], bfh[nt]);
                    mma_bf16(acc[mt][nt], afh[mt], bfl[nt]);
                    mma_bf16(acc[mt][nt], afl[mt], bfh[nt]);
                }
        }
        __syncthreads();
    }

    const long crow0 = (long)blockIdx.x * 128;
    const int  cn0   = blockIdx.y * BN;
#pragma unroll
    for (int mt = 0; mt < 2; mt++) {
        int r = wm * 32 + mt * 16 + (lane >> 2);
#pragma unroll
        for (int nt = 0; nt < NT; nt++) {
            int c = cn0 + wn * WN + nt * 8 + (lane & 3) * 2;
            float2 v0 = make_float2(acc[mt][nt][0], acc[mt][nt][1]);
            float2 v1 = make_float2(acc[mt][nt][2], acc[mt][nt][3]);
            if (BIAS) {
                float b0v = bias[c], b1v = bias[c + 1];
                v0.x += b0v; v0.y += b1v; v1.x += b0v; v1.y += b1v;
            }
            if (RELU) {
                v0.x = fmaxf(v0.x, 0.f); v0.y = fmaxf(v0.y, 0.f);
                v1.x = fmaxf(v1.x, 0.f); v1.y = fmaxf(v1.y, 0.f);
            }
            if (SPLITOUT) {
                __nv_bfloat16 h0, l0, h1, l1, h2, l2, h3, l3;
                split1(v0.x, h0, l0); split1(v0.y, h1, l1);
                split1(v1.x, h2, l2); split1(v1.y, h3, l3);
                size_t o0 = (size_t)(crow0 + r) * ldc + c;
                size_t o1 = (size_t)(crow0 + r + 8) * ldc + c;
                __nv_bfloat162 t;
                t.x = h0; t.y = h1; *(__nv_bfloat162*)&Ohi[o0] = t;
                t.x = l0; t.y = l1; *(__nv_bfloat162*)&Olo[o0] = t;
                t.x = h2; t.y = h3; *(__nv_bfloat162*)&Ohi[o1] = t;
                t.x = l2; t.y = l3; *(__nv_bfloat162*)&Olo[o1] = t;
            } else {
                *(float2*)&C[z * scz + (crow0 + r) * ldc + c]     = v0;
                *(float2*)&C[z * scz + (crow0 + r + 8) * ldc + c] = v1;
            }
        }
    }
}

// ---------------- Launch ----------------
extern "C" void kernel_launch(void* const* d_in, const int* in_sizes, int n_in,
                              void* d_out, int out_size) {
    const float* x   = (const float*)d_in[0];
    const float* Wr0 = (const float*)d_in[1];
    const float* We0 = (const float*)d_in[2];
    const float* b0  = (const float*)d_in[3];
    const float* Wr1 = (const float*)d_in[4];
    const float* We1 = (const float*)d_in[5];
    const float* b1  = (const float*)d_in[6];
    const float* Wr2 = (const float*)d_in[7];
    const float* We2 = (const float*)d_in[8];
    const float* b2  = (const float*)d_in[9];
    const float* Wr3 = (const float*)d_in[10];
    const float* We3 = (const float*)d_in[11];
    const float* b3  = (const float*)d_in[12];
    float* out = (float*)d_out;

    float *hbuf;
    __nv_bfloat16 *ahi, *alo, *whi, *wlo, *Hhi, *Hlo;
    cudaGetSymbolAddress((void**)&hbuf, g_hbuf);
    cudaGetSymbolAddress((void**)&ahi,  g_hcat_hi);
    cudaGetSymbolAddress((void**)&alo,  g_hcat_lo);
    cudaGetSymbolAddress((void**)&whi,  g_whi);
    cudaGetSymbolAddress((void**)&wlo,  g_wlo);
    cudaGetSymbolAddress((void**)&Hhi,  g_Hhi);
    cudaGetSymbolAddress((void**)&Hlo,  g_Hlo);

    const int SZ128 = 2 * (32768 + 2 * 128 * 128);  // 131072
    const int SZ64  = 2 * (32768 + 2 * 64 * 128);   // 98304
    cudaFuncSetAttribute(mma_gemm<128, true, true, false>,   cudaFuncAttributeMaxDynamicSharedMemorySize, SZ128);
    cudaFuncSetAttribute(mma_gemm<64, false, true, true>,    cudaFuncAttributeMaxDynamicSharedMemorySize, SZ64);
    cudaFuncSetAttribute(mma_gemm<128, false, false, false>, cudaFuncAttributeMaxDynamicSharedMemorySize, SZ128);

    zero_indeg<<<(NODES + 255) / 256, 256>>>();
    pack_a<<<(8192 + 65536 + 255) / 256, 256>>>(Wr0, We0, Wr1, We1);
    pack_b<<<(131072 + 32768 + 255) / 256, 256>>>(Wr2, We2, Wr3, We3);

    // kNN: phase 1 (4th launch = ncu capture slot), then merge
    knn_part<<<dim3(4, JCHUNK, BATCH), 256>>>(x);
    knn_merge<<<(NODES + 255) / 256, 256>>>();

    alloc_off<<<(NODES + 255) / 256, 256>>>();
    fill_rev<<<(EDGES + 255) / 256, 256>>>();

    // layers
    build0<<<NODES, 64>>>(x);
    mma_gemm<128, true, true, false><<<dim3(128, 1, 1), 512, SZ128>>>(
        ahi, alo, whi + WO0, wlo + WO0, b0, hbuf, nullptr, nullptr, 64, 128, 0, 0, 0);
    build_split<128><<<NODES, 32>>>(hbuf);
    mma_gemm<128, true, true, false><<<dim3(128, 2, 1), 512, SZ128>>>(
        ahi, alo, whi + WO1, wlo + WO1, b1, hbuf, nullptr, nullptr, 256, 256, 0, 0, 0);
    build_split<256><<<NODES, 64>>>(hbuf);
    mma_gemm<128, true, true, false><<<dim3(128, 2, 1), 512, SZ128>>>(
        ahi, alo, whi + WO2, wlo + WO2, b2, hbuf, nullptr, nullptr, 512, 256, 0, 0, 0);
    build_split<256><<<NODES, 64>>>(hbuf);
    mma_gemm<64, false, true, true><<<dim3(128, 1, 1), 512, SZ64>>>(
        ahi, alo, whi + WO3, wlo + WO3, b3, nullptr, Hhi, Hlo, 512, 64, 0, 0, 0);

    // gram: out[b] = H_b * H_b^T
    mma_gemm<128, false, false, false><<<dim3(8, 8, BATCH), 512, SZ128>>>(
        Hhi, Hlo, Hhi, Hlo, nullptr, out, nullptr, nullptr,
        64, NPTS, NPTS, NPTS, (long)NPTS * NPTS);
}

// round 8
// speedup vs baseline: 2.5903x; 1.1463x over previous
#include <cuda_runtime.h>
#include <cuda_bf16.h>
#include <math.h>
#include <stdint.h>

// ---------------- Problem constants ----------------
#define BATCH   16
#define NPTS    1024
#define CIN     16
#define NODES   (BATCH * NPTS)      // 16384
#define KNN     10
#define EDGES   (NODES * KNN)       // 163840
#define JCHUNK  8                   // candidate-axis partitions
#define JTILE   (NPTS / JCHUNK)     // 128 candidates per tile

// packed weight offsets in bf16 hi/lo arrays, layout [N][Kpad] row-major
#define WO0 0
#define WO1 8192
#define WO2 73728
#define WO3 204800
#define WTOT 237568

// ---------------- Device scratch ----------------
__device__ float          g_hbuf[NODES * 256];
__device__ __nv_bfloat16  g_hcat_hi[NODES * 512];
__device__ __nv_bfloat16  g_hcat_lo[NODES * 512];
__device__ __nv_bfloat16  g_whi[WTOT];
__device__ __nv_bfloat16  g_wlo[WTOT];
__device__ __nv_bfloat16  g_Hhi[NODES * 64];
__device__ __nv_bfloat16  g_Hlo[NODES * 64];
__device__ float g_pd[NODES * JCHUNK * 11];
__device__ int   g_pi[NODES * JCHUNK * 11];
__device__ int g_nbr[EDGES];
__device__ int g_indeg[NODES];
__device__ int g_off[NODES];
__device__ int g_cur[NODES];
__device__ int g_rsrc[EDGES];
__device__ int g_ctr;

// ---------------- PTX helpers (sm_80-era only) ----------------
__device__ __forceinline__ uint32_t smem_u32(const void* p) {
    uint32_t a;
    asm("{ .reg .u64 t; cvta.to.shared.u64 t, %1; cvt.u32.u64 %0, t; }" : "=r"(a) : "l"(p));
    return a;
}
__device__ __forceinline__ void ldsm_x4(uint32_t* r, uint32_t addr) {
    asm volatile("ldmatrix.sync.aligned.m8n8.x4.shared.b16 {%0,%1,%2,%3}, [%4];"
                 : "=r"(r[0]), "=r"(r[1]), "=r"(r[2]), "=r"(r[3]) : "r"(addr));
}
__device__ __forceinline__ void ldsm_x2(uint32_t* r, uint32_t addr) {
    asm volatile("ldmatrix.sync.aligned.m8n8.x2.shared.b16 {%0,%1}, [%2];"
                 : "=r"(r[0]), "=r"(r[1]) : "r"(addr));
}
__device__ __forceinline__ void mma_bf16(float* d, const uint32_t* a, const uint32_t* b) {
    asm volatile(
        "mma.sync.aligned.m16n8k16.row.col.f32.bf16.bf16.f32 "
        "{%0,%1,%2,%3}, {%4,%5,%6,%7}, {%8,%9}, {%0,%1,%2,%3};"
        : "+f"(d[0]), "+f"(d[1]), "+f"(d[2]), "+f"(d[3])
        : "r"(a[0]), "r"(a[1]), "r"(a[2]), "r"(a[3]), "r"(b[0]), "r"(b[1]));
}
__device__ __forceinline__ void cpa16(uint32_t s, const void* g) {
    asm volatile("cp.async.cg.shared.global [%0], [%1], 16;" :: "r"(s), "l"(g) : "memory");
}
__device__ __forceinline__ void cpa_commit() {
    asm volatile("cp.async.commit_group;" ::: "memory");
}

// ---------------- init ----------------
__global__ void zero_indeg() {
    int idx = blockIdx.x * blockDim.x + threadIdx.x;
    if (idx < NODES) g_indeg[idx] = 0;
    if (idx == 0) g_ctr = 0;
}

// ---------------- fused weight pack (bf16 hi/lo split) ----------------
__device__ __forceinline__ void split1(float v, __nv_bfloat16& hi, __nv_bfloat16& lo) {
    hi = __float2bfloat16(v);
    lo = __float2bfloat16(v - __bfloat162float(hi));
}
__device__ __forceinline__ void pack_one(const float* Wr, const float* We,
                                         int K, int Kpad, int idx, int off) {
    int n = idx / Kpad, kk = idx - n * Kpad;
    float v = 0.f;
    if (kk < K) v = Wr[n * K + kk];
    else if (kk < 2 * K) v = We[n * K + kk - K];
    __nv_bfloat16 h, l; split1(v, h, l);
    g_whi[off + idx] = h; g_wlo[off + idx] = l;
}
__global__ void pack_a(const float* __restrict__ Wr0, const float* __restrict__ We0,
                       const float* __restrict__ Wr1, const float* __restrict__ We1) {
    int idx = blockIdx.x * blockDim.x + threadIdx.x;
    if (idx < 8192) pack_one(Wr0, We0, 16, 64, idx, WO0);
    else if (idx < 8192 + 65536) pack_one(Wr1, We1, 128, 256, idx - 8192, WO1);
}
__global__ void pack_b(const float* __restrict__ Wr2, const float* __restrict__ We2,
                       const float* __restrict__ Wr3, const float* __restrict__ We3) {
    int idx = blockIdx.x * blockDim.x + threadIdx.x;
    if (idx < 131072) pack_one(Wr2, We2, 256, 512, idx, WO2);
    else if (idx < 131072 + 32768) pack_one(Wr3, We3, 256, 512, idx - 131072, WO3);
}

// ---------------- strict-< sorted insert (tie-break preserved by ascending-j order) ----------------
#define STRICT_INSERT(sd, si, d2, j) do {                                          \
    if ((d2) < sd[10]) {                                                           \
        sd[10] = (d2); si[10] = (j);                                               \
        _Pragma("unroll")                                                          \
        for (int _t = 10; _t > 0; _t--) {                                          \
            bool _sw = sd[_t] < sd[_t-1];                                          \
            float _da = sd[_t], _db = sd[_t-1];                                    \
            int   _ia = si[_t], _ib = si[_t-1];                                    \
            sd[_t-1] = _sw ? _da : _db; si[_t-1] = _sw ? _ia : _ib;                \
            sd[_t]   = _sw ? _db : _da; si[_t]   = _sw ? _ib : _ia;                \
        }                                                                          \
    }                                                                              \
} while (0)

// ---------------- kNN phase 1: partial top-11 over a 128-candidate chunk ----------------
// grid (4 ichunks, JCHUNK jchunks, BATCH), block 256
__global__ void knn_part(const float* __restrict__ x) {
    const int b   = blockIdx.z;
    const int tid = threadIdx.x;
    const int i   = blockIdx.x * 256 + tid;
    const int j0  = blockIdx.y * JTILE;
    const float* xb = x + (size_t)b * NPTS * CIN;

    __shared__ float sx[JTILE * 16];
    __shared__ float ssq[JTILE];

    float xi[16]; float sqi = 0.f;
#pragma unroll
    for (int c = 0; c < 16; c++) { xi[c] = xb[i * 16 + c]; sqi += xi[c] * xi[c]; }

    if (tid < JTILE) {
        float s = 0.f;
#pragma unroll
        for (int c = 0; c < 16; c++) {
            float v = xb[(j0 + tid) * 16 + c];
            sx[tid * 16 + c] = v;
            s += v * v;
        }
        ssq[tid] = s;
    }
    __syncthreads();

    float sd[11]; int si[11];
#pragma unroll
    for (int t = 0; t < 11; t++) { sd[t] = INFINITY; si[t] = 0x7fffffff; }

    for (int jj = 0; jj < JTILE; jj++) {
        float dot = 0.f;
#pragma unroll
        for (int c = 0; c < 16; c++) dot += xi[c] * sx[jj * 16 + c];
        float d2 = sqi + ssq[jj] - 2.0f * dot;
        int   j  = j0 + jj;
        STRICT_INSERT(sd, si, d2, j);
    }

    const size_t base = ((size_t)(b * NPTS + i) * JCHUNK + blockIdx.y) * 11;
#pragma unroll
    for (int t = 0; t < 11; t++) { g_pd[base + t] = sd[t]; g_pi[base + t] = si[t]; }
}

// ---------------- kNN phase 2: merge JCHUNK sorted 11-lists, emit neighbors ----------------
__global__ void knn_merge() {
    int g = blockIdx.x * blockDim.x + threadIdx.x;
    if (g >= NODES) return;
    const size_t base = (size_t)g * JCHUNK * 11;

    float sd[11]; int si[11];
#pragma unroll
    for (int t = 0; t < 11; t++) { sd[t] = g_pd[base + t]; si[t] = g_pi[base + t]; }
#pragma unroll
    for (int q = 1; q < JCHUNK; q++) {
#pragma unroll
        for (int u = 0; u < 11; u++) {
            float d2 = g_pd[base + q * 11 + u];
            int   j  = g_pi[base + q * 11 + u];
            STRICT_INSERT(sd, si, d2, j);
        }
    }
    int boff = (g / NPTS) * NPTS;
#pragma unroll
    for (int t = 1; t <= 10; t++) {
        int nb = boff + si[t];
        g_nbr[g * KNN + (t - 1)] = nb;
        atomicAdd(&g_indeg[nb], 1);
    }
}

// ---------------- atomic CSR range allocation ----------------
__global__ void alloc_off() {
    int m = blockIdx.x * blockDim.x + threadIdx.x;
    if (m < NODES) {
        int d = g_indeg[m];
        int p = atomicAdd(&g_ctr, d);
        g_off[m] = p;
        g_cur[m] = p;
    }
}
__global__ void fill_rev() {
    int e = blockIdx.x * blockDim.x + threadIdx.x;
    if (e < EDGES) {
        int m = g_nbr[e];
        int p = atomicAdd(&g_cur[m], 1);
        g_rsrc[p] = e / KNN;
    }
}

// ---------------- build [own | agg] (multi-node blocks) ----------------
// L0: 256 threads = 4 nodes x 64 lanes
__global__ void build0(const float* __restrict__ x) {
    int t = threadIdx.x;
    int m = blockIdx.x * 4 + (t >> 6);
    int c = t & 63;
    float v = 0.f;
    if (c < 16) v = x[(size_t)m * 16 + c];
    else if (c < 32) {
        int cc = c - 16; float s = 0.f;
        int e0 = g_off[m], e1 = e0 + g_indeg[m];
        for (int e = e0; e < e1; e++) s += x[(size_t)g_rsrc[e] * 16 + cc];
        v = s;
    }
    __nv_bfloat16 h, l; split1(v, h, l);
    g_hcat_hi[(size_t)m * 64 + c] = h;
    g_hcat_lo[(size_t)m * 64 + c] = l;
}
// 256 threads = NPB nodes x (K/4) lanes
template <int K>
__global__ void build_split(const float* __restrict__ h) {
    constexpr int TPN = K / 4;
    constexpr int NPB = 256 / TPN;
    int t = threadIdx.x;
    int m = blockIdx.x * NPB + t / TPN;
    int c = t % TPN;
    const int kq = K / 4;
    const float4* h4 = (const float4*)h;
    float4 own = h4[(size_t)m * kq + c];
    float4 s = make_float4(0.f, 0.f, 0.f, 0.f);
    int e0 = g_off[m], e1 = e0 + g_indeg[m];
    for (int e = e0; e < e1; e++) {
        float4 v = h4[(size_t)g_rsrc[e] * kq + c];
        s.x += v.x; s.y += v.y; s.z += v.z; s.w += v.w;
    }
    size_t r = (size_t)m * (2 * K);
    const float* ov = &own.x;
    const float* sv = &s.x;
#pragma unroll
    for (int j = 0; j < 4; j++) {
        __nv_bfloat16 h1, l1; split1(ov[j], h1, l1);
        g_hcat_hi[r + c * 4 + j] = h1; g_hcat_lo[r + c * 4 + j] = l1;
        __nv_bfloat16 h2, l2; split1(sv[j], h2, l2);
        g_hcat_hi[r + K + c * 4 + j] = h2; g_hcat_lo[r + K + c * 4 + j] = l2;
    }
}

// ---------------- mma.sync bf16x3 GEMM, cp.async double-buffered ----------------
template <int BN, bool RELU, bool BIAS, bool SPLITOUT>
__global__ void __launch_bounds__(512)
mma_gemm(const __nv_bfloat16* __restrict__ Ahi, const __nv_bfloat16* __restrict__ Alo,
         const __nv_bfloat16* __restrict__ Bhi, const __nv_bfloat16* __restrict__ Blo,
         const float* __restrict__ bias, float* __restrict__ C,
         __nv_bfloat16* __restrict__ Ohi, __nv_bfloat16* __restrict__ Olo,
         int K, int ldc, long saz, long sbz, long scz) {
    extern __shared__ char smraw[];
    constexpr int OFF_AL = 16384;
    constexpr int OFF_BH = 32768;
    constexpr int OFF_BL = 32768 + BN * 128;
    constexpr int STAGE  = 32768 + 2 * BN * 128;

    const int tid = threadIdx.x;
    const int wid = tid >> 5, lane = tid & 31;
    const int wm = wid >> 2, wn = wid & 3;
    constexpr int WN = BN / 4;
    constexpr int NT = WN / 8;

    const long z     = blockIdx.z;
    const long arow0 = z * saz + (long)blockIdx.x * 128;
    const long brow0 = z * sbz + (long)blockIdx.y * BN;

    const uint32_t uSm = smem_u32(smraw);

    float acc[2][NT][4];
#pragma unroll
    for (int i = 0; i < 2; i++)
#pragma unroll
        for (int j = 0; j < NT; j++)
#pragma unroll
            for (int q = 0; q < 4; q++) acc[i][j][q] = 0.f;

    const int nko = K >> 6;
    constexpr int CH = (128 + BN) * 8;

    auto stage = [&](int ko, int buf) {
        const uint32_t base = uSm + buf * STAGE;
#pragma unroll
        for (int it = 0; it < CH / 512; it++) {
            int idx = tid + it * 512;
            int r = idx >> 3, c = idx & 7;
            if (r < 128) {
                int pc = c ^ (r & 7);
                size_t go = (size_t)(arow0 + r) * K + ko * 64 + c * 8;
                cpa16(base + r * 128 + pc * 16, Ahi + go);
                cpa16(base + OFF_AL + r * 128 + pc * 16, Alo + go);
            } else {
                int rb = r - 128, prb = c ^ (rb & 7);
                size_t go = (size_t)(brow0 + rb) * K + ko * 64 + c * 8;
                cpa16(base + OFF_BH + rb * 128 + prb * 16, Bhi + go);
                cpa16(base + OFF_BL + rb * 128 + prb * 16, Blo + go);
            }
        }
        cpa_commit();
    };

    stage(0, 0);
    for (int ko = 0; ko < nko; ko++) {
        if (ko + 1 < nko) {
            stage(ko + 1, (ko + 1) & 1);
            asm volatile("cp.async.wait_group 1;" ::: "memory");
        } else {
            asm volatile("cp.async.wait_group 0;" ::: "memory");
        }
        __syncthreads();

        const uint32_t base = uSm + (ko & 1) * STAGE;
        const uint32_t uAh = base, uAl = base + OFF_AL;
        const uint32_t uBh = base + OFF_BH, uBl = base + OFF_BL;
#pragma unroll
        for (int k16 = 0; k16 < 4; k16++) {
            uint32_t afh[2][4], afl[2][4];
#pragma unroll
            for (int mt = 0; mt < 2; mt++) {
                int row = wm * 32 + mt * 16 + (lane & 15);
                int ch = (k16 * 2 + (lane >> 4)) ^ (row & 7);
                uint32_t off = (uint32_t)(row * 128 + ch * 16);
                ldsm_x4(afh[mt], uAh + off);
                ldsm_x4(afl[mt], uAl + off);
            }
            uint32_t bfh[NT][2], bfl[NT][2];
#pragma unroll
            for (int nt = 0; nt < NT; nt++) {
                int n = wn * WN + nt * 8 + (lane & 7);
                int ch = (k16 * 2 + ((lane >> 3) & 1)) ^ (n & 7);
                uint32_t off = (uint32_t)(n * 128 + ch * 16);
                ldsm_x2(bfh[nt], uBh + off);
                ldsm_x2(bfl[nt], uBl + off);
            }
#pragma unroll
            for (int mt = 0; mt < 2; mt++)
#pragma unroll
                for (int nt = 0; nt < NT; nt++) {
                    mma_bf16(acc[mt][nt], afh[mt], bfh[nt]);
                    mma_bf16(acc[mt][nt], afh[mt], bfl[nt]);
                    mma_bf16(acc[mt][nt], afl[mt], bfh[nt]);
                }
        }
        __syncthreads();
    }

    const long crow0 = (long)blockIdx.x * 128;
    const int  cn0   = blockIdx.y * BN;
#pragma unroll
    for (int mt = 0; mt < 2; mt++) {
        int r = wm * 32 + mt * 16 + (lane >> 2);
#pragma unroll
        for (int nt = 0; nt < NT; nt++) {
            int c = cn0 + wn * WN + nt * 8 + (lane & 3) * 2;
            float2 v0 = make_float2(acc[mt][nt][0], acc[mt][nt][1]);
            float2 v1 = make_float2(acc[mt][nt][2], acc[mt][nt][3]);
            if (BIAS) {
                float b0v = bias[c], b1v = bias[c + 1];
                v0.x += b0v; v0.y += b1v; v1.x += b0v; v1.y += b1v;
            }
            if (RELU) {
                v0.x = fmaxf(v0.x, 0.f); v0.y = fmaxf(v0.y, 0.f);
                v1.x = fmaxf(v1.x, 0.f); v1.y = fmaxf(v1.y, 0.f);
            }
            if (SPLITOUT) {
                __nv_bfloat16 h0, l0, h1, l1, h2, l2, h3, l3;
                split1(v0.x, h0, l0); split1(v0.y, h1, l1);
                split1(v1.x, h2, l2); split1(v1.y, h3, l3);
                size_t o0 = (size_t)(crow0 + r) * ldc + c;
                size_t o1 = (size_t)(crow0 + r + 8) * ldc + c;
                __nv_bfloat162 t;
                t.x = h0; t.y = h1; *(__nv_bfloat162*)&Ohi[o0] = t;
                t.x = l0; t.y = l1; *(__nv_bfloat162*)&Olo[o0] = t;
                t.x = h2; t.y = h3; *(__nv_bfloat162*)&Ohi[o1] = t;
                t.x = l2; t.y = l3; *(__nv_bfloat162*)&Olo[o1] = t;
            } else {
                *(float2*)&C[z * scz + (crow0 + r) * ldc + c]     = v0;
                *(float2*)&C[z * scz + (crow0 + r + 8) * ldc + c] = v1;
            }
        }
    }
}

// ---------------- Launch ----------------
extern "C" void kernel_launch(void* const* d_in, const int* in_sizes, int n_in,
                              void* d_out, int out_size) {
    const float* x   = (const float*)d_in[0];
    const float* Wr0 = (const float*)d_in[1];
    const float* We0 = (const float*)d_in[2];
    const float* b0  = (const float*)d_in[3];
    const float* Wr1 = (const float*)d_in[4];
    const float* We1 = (const float*)d_in[5];
    const float* b1  = (const float*)d_in[6];
    const float* Wr2 = (const float*)d_in[7];
    const float* We2 = (const float*)d_in[8];
    const float* b2  = (const float*)d_in[9];
    const float* Wr3 = (const float*)d_in[10];
    const float* We3 = (const float*)d_in[11];
    const float* b3  = (const float*)d_in[12];
    float* out = (float*)d_out;

    float *hbuf;
    __nv_bfloat16 *ahi, *alo, *whi, *wlo, *Hhi, *Hlo;
    cudaGetSymbolAddress((void**)&hbuf, g_hbuf);
    cudaGetSymbolAddress((void**)&ahi,  g_hcat_hi);
    cudaGetSymbolAddress((void**)&alo,  g_hcat_lo);
    cudaGetSymbolAddress((void**)&whi,  g_whi);
    cudaGetSymbolAddress((void**)&wlo,  g_wlo);
    cudaGetSymbolAddress((void**)&Hhi,  g_Hhi);
    cudaGetSymbolAddress((void**)&Hlo,  g_Hlo);

    const int SZ128 = 2 * (32768 + 2 * 128 * 128);  // 131072
    const int SZ64  = 2 * (32768 + 2 * 64 * 128);   // 98304
    cudaFuncSetAttribute(mma_gemm<128, true, true, false>,   cudaFuncAttributeMaxDynamicSharedMemorySize, SZ128);
    cudaFuncSetAttribute(mma_gemm<64, false, true, true>,    cudaFuncAttributeMaxDynamicSharedMemorySize, SZ64);
    cudaFuncSetAttribute(mma_gemm<128, false, false, false>, cudaFuncAttributeMaxDynamicSharedMemorySize, SZ128);

    zero_indeg<<<(NODES + 255) / 256, 256>>>();
    pack_a<<<(8192 + 65536 + 255) / 256, 256>>>(Wr0, We0, Wr1, We1);
    pack_b<<<(131072 + 32768 + 255) / 256, 256>>>(Wr2, We2, Wr3, We3);

    // kNN: phase 1 (4th launch = ncu capture slot), then merge
    knn_part<<<dim3(4, JCHUNK, BATCH), 256>>>(x);
    knn_merge<<<(NODES + 255) / 256, 256>>>();

    alloc_off<<<(NODES + 255) / 256, 256>>>();
    fill_rev<<<(EDGES + 255) / 256, 256>>>();

    // layers
    build0<<<NODES / 4, 256>>>(x);
    mma_gemm<128, true, true, false><<<dim3(128, 1, 1), 512, SZ128>>>(
        ahi, alo, whi + WO0, wlo + WO0, b0, hbuf, nullptr, nullptr, 64, 128, 0, 0, 0);
    build_split<128><<<NODES / 8, 256>>>(hbuf);
    mma_gemm<128, true, true, false><<<dim3(128, 2, 1), 512, SZ128>>>(
        ahi, alo, whi + WO1, wlo + WO1, b1, hbuf, nullptr, nullptr, 256, 256, 0, 0, 0);
    build_split<256><<<NODES / 4, 256>>>(hbuf);
    mma_gemm<128, true, true, false><<<dim3(128, 2, 1), 512, SZ128>>>(
        ahi, alo, whi + WO2, wlo + WO2, b2, hbuf, nullptr, nullptr, 512, 256, 0, 0, 0);
    build_split<256><<<NODES / 4, 256>>>(hbuf);
    mma_gemm<64, false, true, true><<<dim3(128, 1, 1), 512, SZ64>>>(
        ahi, alo, whi + WO3, wlo + WO3, b3, nullptr, Hhi, Hlo, 512, 64, 0, 0, 0);

    // gram: out[b] = H_b * H_b^T
    mma_gemm<128, false, false, false><<<dim3(8, 8, BATCH), 512, SZ128>>>(
        Hhi, Hlo, Hhi, Hlo, nullptr, out, nullptr, nullptr,
        64, NPTS, NPTS, NPTS, (long)NPTS * NPTS);
}